// round 3
// baseline (speedup 1.0000x reference)
#include <cuda_runtime.h>
#include <cstdint>

// Problem constants
#define BSZ   2
#define SEQ   2048
#define DMODEL 2048
#define NH    32
#define NKVH  8
#define HDIM  64
#define QK_SCALE 0.125f   // 64^-0.5
#define MROWS (BSZ*SEQ)   // 4096

// -------- scratch (static device globals: allocation-free) --------
__device__ float g_Q[(size_t)MROWS * NH * HDIM];     // 32 MB
__device__ float g_K[(size_t)MROWS * NKVH * HDIM];   //  8 MB
__device__ float g_V[(size_t)MROWS * NKVH * HDIM];   //  8 MB
__device__ float g_O[(size_t)MROWS * NH * HDIM];     // 32 MB

// ===================================================================
// NT SGEMM: C[M,N] = A[M,K] @ W[N,K]^T   (both K-contiguous row-major)
// 128x128x16 tiles, 256 threads, 8x8 micro-tile
// ===================================================================
__global__ void __launch_bounds__(256)
sgemm_nt(const float* __restrict__ A, const float* __restrict__ W,
         float* __restrict__ C, int M, int N, int K)
{
    __shared__ float As[16][132];
    __shared__ float Bs[16][132];

    const int tid = threadIdx.x;
    const int tx  = tid & 15;       // n dim
    const int ty  = tid >> 4;       // m dim
    const int m0  = blockIdx.y << 7;
    const int n0  = blockIdx.x << 7;

    float acc[8][8];
#pragma unroll
    for (int i = 0; i < 8; i++)
#pragma unroll
        for (int j = 0; j < 8; j++) acc[i][j] = 0.f;

    const int row_l = tid >> 2;     // 0..63
    const int qk    = tid & 3;      // k-quad

    for (int k0 = 0; k0 < K; k0 += 16) {
#pragma unroll
        for (int p = 0; p < 2; p++) {
            int row = row_l + p * 64;
            float4 va = *(const float4*)(A + (size_t)(m0 + row) * K + k0 + qk * 4);
            As[qk * 4 + 0][row] = va.x;
            As[qk * 4 + 1][row] = va.y;
            As[qk * 4 + 2][row] = va.z;
            As[qk * 4 + 3][row] = va.w;
            float4 vb = *(const float4*)(W + (size_t)(n0 + row) * K + k0 + qk * 4);
            Bs[qk * 4 + 0][row] = vb.x;
            Bs[qk * 4 + 1][row] = vb.y;
            Bs[qk * 4 + 2][row] = vb.z;
            Bs[qk * 4 + 3][row] = vb.w;
        }
        __syncthreads();

#pragma unroll
        for (int kk = 0; kk < 16; kk++) {
            float a[8], b[8];
#pragma unroll
            for (int i = 0; i < 4; i++) {
                a[i]     = As[kk][ty * 4 + i];
                a[4 + i] = As[kk][64 + ty * 4 + i];
                b[i]     = Bs[kk][tx * 4 + i];
                b[4 + i] = Bs[kk][64 + tx * 4 + i];
            }
#pragma unroll
            for (int i = 0; i < 8; i++)
#pragma unroll
                for (int j = 0; j < 8; j++)
                    acc[i][j] += a[i] * b[j];
        }
        __syncthreads();
    }

#pragma unroll
    for (int i = 0; i < 8; i++) {
        int m = m0 + ((i < 4) ? (ty * 4 + i) : (64 + ty * 4 + (i - 4)));
        float4 c0 = make_float4(acc[i][0], acc[i][1], acc[i][2], acc[i][3]);
        float4 c1 = make_float4(acc[i][4], acc[i][5], acc[i][6], acc[i][7]);
        *(float4*)(C + (size_t)m * N + n0 + tx * 4)      = c0;
        *(float4*)(C + (size_t)m * N + n0 + 64 + tx * 4) = c1;
    }
}

// ===================================================================
// RoPE in-place. X: [B*S, heads*64]; cos/sin: [B*S, 64]
// one thread per (row, head, d<32) pair -> writes d and d+32 (race-free)
// ===================================================================
__global__ void rope_kernel(float* __restrict__ X,
                            const float* __restrict__ cs,
                            const float* __restrict__ sn,
                            int heads, int total)
{
    int idx = blockIdx.x * blockDim.x + threadIdx.x;
    if (idx >= total) return;
    int d   = idx & 31;
    int hh  = (idx >> 5) % heads;
    int row = idx / (heads * 32);

    float c1 = cs[row * 64 + d];
    float s1 = sn[row * 64 + d];
    float c2 = cs[row * 64 + d + 32];
    float s2 = sn[row * 64 + d + 32];

    float* p = X + (size_t)row * heads * 64 + hh * 64;
    float x1 = p[d], x2 = p[d + 32];
    p[d]      = x1 * c1 - x2 * s1;   // x*cos + (-x2)*sin
    p[d + 32] = x2 * c2 + x1 * s2;   // x*cos + ( x1)*sin
}

// ===================================================================
// Flash attention fp32, causal, GQA (G=4).
// Tile 64(q) x 64(kv), DH=64. 256 threads, 4x4 micro-tiles.
// Shared: Qs, KPs (K reused for P), Vs -- each [64][68] floats.
// ===================================================================
#define LDS_ 68

__global__ void __launch_bounds__(256)
flash_kernel(const float* __restrict__ Qg, const float* __restrict__ Kg,
             const float* __restrict__ Vg, float* __restrict__ Og)
{
    extern __shared__ float sm[];
    float* Qs  = sm;
    float* KPs = sm + 64 * LDS_;
    float* Vs  = sm + 2 * 64 * LDS_;

    const int qt  = blockIdx.x;   // q tile
    const int h   = blockIdx.y;
    const int b   = blockIdx.z;
    const int kvh = h >> 2;       // G = 4

    const int tid = threadIdx.x;
    const int tx  = tid & 15;
    const int ty  = tid >> 4;
    const int R0  = ty * 4;
    const int C0  = tx * 4;

    const int lrow  = tid >> 4;   // 0..15 (load row within pass)
    const int lquad = tid & 15;   // 0..15 (16B quad)

    // ---- load Q tile (pre-scaled) ----
    {
        const float* src = Qg + ((size_t)(b * SEQ + qt * 64)) * (NH * HDIM) + h * HDIM;
#pragma unroll
        for (int p = 0; p < 4; p++) {
            int row = p * 16 + lrow;
            float4 v = *(const float4*)(src + (size_t)row * (NH * HDIM) + lquad * 4);
            v.x *= QK_SCALE; v.y *= QK_SCALE; v.z *= QK_SCALE; v.w *= QK_SCALE;
            *(float4*)&Qs[row * LDS_ + lquad * 4] = v;
        }
    }

    float m_r[4], l_r[4], o[4][4];
#pragma unroll
    for (int r = 0; r < 4; r++) {
        m_r[r] = -1e30f;
        l_r[r] = 0.f;
#pragma unroll
        for (int c = 0; c < 4; c++) o[r][c] = 0.f;
    }

    const float* ksrc = Kg + ((size_t)(b * SEQ)) * (NKVH * HDIM) + kvh * HDIM;
    const float* vsrc = Vg + ((size_t)(b * SEQ)) * (NKVH * HDIM) + kvh * HDIM;

    for (int j = 0; j <= qt; j++) {
        __syncthreads();   // Qs ready (j=0) / previous PV done reading KPs,Vs
#pragma unroll
        for (int p = 0; p < 4; p++) {
            int row = p * 16 + lrow;
            *(float4*)&KPs[row * LDS_ + lquad * 4] =
                *(const float4*)(ksrc + (size_t)(j * 64 + row) * (NKVH * HDIM) + lquad * 4);
            *(float4*)&Vs[row * LDS_ + lquad * 4] =
                *(const float4*)(vsrc + (size_t)(j * 64 + row) * (NKVH * HDIM) + lquad * 4);
        }
        __syncthreads();

        // ---- scores: S = (scaled Q) @ K^T ----
        float s[4][4];
#pragma unroll
        for (int r = 0; r < 4; r++)
#pragma unroll
            for (int c = 0; c < 4; c++) s[r][c] = 0.f;

#pragma unroll
        for (int d = 0; d < 64; d += 4) {
            float4 q4[4], k4[4];
#pragma unroll
            for (int r = 0; r < 4; r++) q4[r] = *(float4*)&Qs[(R0 + r) * LDS_ + d];
#pragma unroll
            for (int c = 0; c < 4; c++) k4[c] = *(float4*)&KPs[(C0 + c) * LDS_ + d];
#pragma unroll
            for (int r = 0; r < 4; r++)
#pragma unroll
                for (int c = 0; c < 4; c++)
                    s[r][c] += q4[r].x * k4[c].x + q4[r].y * k4[c].y +
                               q4[r].z * k4[c].z + q4[r].w * k4[c].w;
        }

        // ---- causal mask on diagonal tile ----
        if (j == qt) {
#pragma unroll
            for (int r = 0; r < 4; r++)
#pragma unroll
                for (int c = 0; c < 4; c++)
                    if (C0 + c > R0 + r) s[r][c] = -1e30f;
        }

        // ---- online softmax ----
#pragma unroll
        for (int r = 0; r < 4; r++) {
            float mx = fmaxf(fmaxf(s[r][0], s[r][1]), fmaxf(s[r][2], s[r][3]));
#pragma unroll
            for (int off = 8; off; off >>= 1)
                mx = fmaxf(mx, __shfl_xor_sync(0xffffffffu, mx, off));
            float mnew  = fmaxf(m_r[r], mx);
            float alpha = __expf(m_r[r] - mnew);
            float sum = 0.f;
#pragma unroll
            for (int c = 0; c < 4; c++) {
                float e = __expf(s[r][c] - mnew);
                s[r][c] = e;
                sum += e;
            }
#pragma unroll
            for (int off = 8; off; off >>= 1)
                sum += __shfl_xor_sync(0xffffffffu, sum, off);
            l_r[r] = l_r[r] * alpha + sum;
            m_r[r] = mnew;
#pragma unroll
            for (int c = 0; c < 4; c++) o[r][c] *= alpha;
        }

        __syncthreads();   // everyone done reading KPs as K
        // ---- write P into KPs ----
#pragma unroll
        for (int r = 0; r < 4; r++)
            *(float4*)&KPs[(R0 + r) * LDS_ + C0] =
                make_float4(s[r][0], s[r][1], s[r][2], s[r][3]);
        __syncthreads();

        // ---- O += P @ V ----
#pragma unroll
        for (int c0 = 0; c0 < 64; c0 += 4) {
            float4 p4[4], v4[4];
#pragma unroll
            for (int r = 0; r < 4; r++) p4[r] = *(float4*)&KPs[(R0 + r) * LDS_ + c0];
#pragma unroll
            for (int i = 0; i < 4; i++) v4[i] = *(float4*)&Vs[(c0 + i) * LDS_ + C0];
#pragma unroll
            for (int r = 0; r < 4; r++) {
                o[r][0] += p4[r].x * v4[0].x + p4[r].y * v4[1].x + p4[r].z * v4[2].x + p4[r].w * v4[3].x;
                o[r][1] += p4[r].x * v4[0].y + p4[r].y * v4[1].y + p4[r].z * v4[2].y + p4[r].w * v4[3].y;
                o[r][2] += p4[r].x * v4[0].z + p4[r].y * v4[1].z + p4[r].z * v4[2].z + p4[r].w * v4[3].z;
                o[r][3] += p4[r].x * v4[0].w + p4[r].y * v4[1].w + p4[r].z * v4[2].w + p4[r].w * v4[3].w;
            }
        }
    }

    // ---- epilogue: normalize + write ----
    float* dst = Og + ((size_t)(b * SEQ + qt * 64)) * (NH * HDIM) + h * HDIM;
#pragma unroll
    for (int r = 0; r < 4; r++) {
        float inv = 1.0f / l_r[r];
        float4 v = make_float4(o[r][0] * inv, o[r][1] * inv, o[r][2] * inv, o[r][3] * inv);
        *(float4*)(dst + (size_t)(R0 + r) * (NH * HDIM) + C0) = v;
    }
}

// ===================================================================
// Launch
// inputs: 0 hidden, 1 cos, 2 sin, 3 attention_mask (unused; pure causal),
//         4 Wq, 5 Wk, 6 Wv, 7 Wo
// ===================================================================
extern "C" void kernel_launch(void* const* d_in, const int* in_sizes, int n_in,
                              void* d_out, int out_size)
{
    const float* hs = (const float*)d_in[0];
    const float* cs = (const float*)d_in[1];
    const float* sn = (const float*)d_in[2];
    const float* Wq = (const float*)d_in[4];
    const float* Wk = (const float*)d_in[5];
    const float* Wv = (const float*)d_in[6];
    const float* Wo = (const float*)d_in[7];
    float* out = (float*)d_out;

    float *Qb, *Kb, *Vb, *Ob;
    cudaGetSymbolAddress((void**)&Qb, g_Q);
    cudaGetSymbolAddress((void**)&Kb, g_K);
    cudaGetSymbolAddress((void**)&Vb, g_V);
    cudaGetSymbolAddress((void**)&Ob, g_O);

    dim3 blk(256);

    // QKV projections
    sgemm_nt<<<dim3((NH * HDIM) / 128, MROWS / 128), blk>>>(hs, Wq, Qb, MROWS, NH * HDIM, DMODEL);
    sgemm_nt<<<dim3((NKVH * HDIM) / 128, MROWS / 128), blk>>>(hs, Wk, Kb, MROWS, NKVH * HDIM, DMODEL);
    sgemm_nt<<<dim3((NKVH * HDIM) / 128, MROWS / 128), blk>>>(hs, Wv, Vb, MROWS, NKVH * HDIM, DMODEL);

    // RoPE
    {
        int totalQ = MROWS * NH * 32;
        rope_kernel<<<(totalQ + 255) / 256, 256>>>(Qb, cs, sn, NH, totalQ);
        int totalK = MROWS * NKVH * 32;
        rope_kernel<<<(totalK + 255) / 256, 256>>>(Kb, cs, sn, NKVH, totalK);
    }

    // Attention
    const int flash_smem = 3 * 64 * LDS_ * (int)sizeof(float);  // 52224 B
    cudaFuncSetAttribute(flash_kernel, cudaFuncAttributeMaxDynamicSharedMemorySize, flash_smem);
    flash_kernel<<<dim3(SEQ / 64, NH, BSZ), 256, flash_smem>>>(Qb, Kb, Vb, Ob);

    // Output projection -> d_out
    sgemm_nt<<<dim3(DMODEL / 128, MROWS / 128), blk>>>(Ob, Wo, out, MROWS, DMODEL, DMODEL);
}

// round 5
// speedup vs baseline: 1.4831x; 1.4831x over previous
#include <cuda_runtime.h>
#include <cuda_bf16.h>
#include <cstdint>

// Problem constants
#define BSZ   2
#define SEQ   2048
#define DMODEL 2048
#define NH    32
#define NKVH  8
#define HDIM  64
#define QK_SCALE 0.125f
#define MROWS (BSZ*SEQ)   // 4096

// -------- scratch (static device globals: allocation-free) --------
__device__ float g_Q[(size_t)MROWS * NH * HDIM];     // 32 MB
__device__ float g_K[(size_t)MROWS * NKVH * HDIM];   //  8 MB
__device__ float g_V[(size_t)MROWS * NKVH * HDIM];   //  8 MB
__device__ float g_O[(size_t)MROWS * NH * HDIM];     // 32 MB
__device__ __nv_bfloat16 g_act_hi[(size_t)MROWS * DMODEL];   // 16.8 MB
__device__ __nv_bfloat16 g_act_lo[(size_t)MROWS * DMODEL];
__device__ __nv_bfloat16 g_w_hi[(size_t)DMODEL * DMODEL];    // 8.4 MB
__device__ __nv_bfloat16 g_w_lo[(size_t)DMODEL * DMODEL];

// ===================================================================
// Helpers (base sm_103-safe: cp.async / ldmatrix / mma.sync only)
// ===================================================================
__device__ __forceinline__ uint32_t smem_u32(const void* p) {
    uint32_t a;
    asm("{ .reg .u64 t; cvta.to.shared.u64 t, %1; cvt.u32.u64 %0, t; }" : "=r"(a) : "l"(p));
    return a;
}
__device__ __forceinline__ void ldm4(uint32_t* r, uint32_t addr) {
    asm volatile("ldmatrix.sync.aligned.m8n8.x4.shared.b16 {%0,%1,%2,%3}, [%4];"
                 : "=r"(r[0]), "=r"(r[1]), "=r"(r[2]), "=r"(r[3]) : "r"(addr));
}
__device__ __forceinline__ void mma16816(float* c, const uint32_t* a,
                                         uint32_t b0, uint32_t b1) {
    asm volatile(
        "mma.sync.aligned.m16n8k16.row.col.f32.bf16.bf16.f32 "
        "{%0,%1,%2,%3}, {%4,%5,%6,%7}, {%8,%9}, {%0,%1,%2,%3};"
        : "+f"(c[0]), "+f"(c[1]), "+f"(c[2]), "+f"(c[3])
        : "r"(a[0]), "r"(a[1]), "r"(a[2]), "r"(a[3]), "r"(b0), "r"(b1));
}

// ===================================================================
// Split fp32 -> bf16 hi + bf16 lo (elementwise, float4 vectorized)
// ===================================================================
__global__ void split_bf16x2(const float* __restrict__ x,
                             __nv_bfloat16* __restrict__ hi,
                             __nv_bfloat16* __restrict__ lo, int n4)
{
    int i = blockIdx.x * blockDim.x + threadIdx.x;
    if (i >= n4) return;
    float4 v = ((const float4*)x)[i];
    __nv_bfloat16 h0 = __float2bfloat16(v.x);
    __nv_bfloat16 h1 = __float2bfloat16(v.y);
    __nv_bfloat16 h2 = __float2bfloat16(v.z);
    __nv_bfloat16 h3 = __float2bfloat16(v.w);
    __nv_bfloat16 l0 = __float2bfloat16(v.x - __bfloat162float(h0));
    __nv_bfloat16 l1 = __float2bfloat16(v.y - __bfloat162float(h1));
    __nv_bfloat16 l2 = __float2bfloat16(v.z - __bfloat162float(h2));
    __nv_bfloat16 l3 = __float2bfloat16(v.w - __bfloat162float(h3));
    __nv_bfloat162* H = (__nv_bfloat162*)hi;
    __nv_bfloat162* L = (__nv_bfloat162*)lo;
    __nv_bfloat162 p;
    p.x = h0; p.y = h1; H[2 * i] = p;
    p.x = h2; p.y = h3; H[2 * i + 1] = p;
    p.x = l0; p.y = l1; L[2 * i] = p;
    p.x = l2; p.y = l3; L[2 * i + 1] = p;
}

// ===================================================================
// Split-bf16 NT GEMM on mma.sync: C[M,N] = A[M,K] @ W[N,K]^T, fp32 acc
// CTA 128x128, k-chunk 32, 8 warps (2m x 4n), warp tile 64x32.
// Smem per stage: 4 buffers (Ahi,Alo,Bhi,Blo), each 128 rows x 80B.
// ===================================================================
#define BUF_B  10240           // 128 * 80
#define STG_B  (4 * BUF_B)     // 40960
#define GEMM_SMEM (2 * STG_B)  // 81920

__device__ __forceinline__ void g2s_chunk(uint32_t sbase,
    const __nv_bfloat16* __restrict__ A0, const __nv_bfloat16* __restrict__ A1,
    const __nv_bfloat16* __restrict__ B0, const __nv_bfloat16* __restrict__ B1,
    int K, int k0, int tid)
{
#pragma unroll
    for (int b = 0; b < 4; b++) {
        const __nv_bfloat16* src =
            (b == 0) ? A0 : (b == 1) ? A1 : (b == 2) ? B0 : B1;
#pragma unroll
        for (int j = 0; j < 2; j++) {
            int idx = tid + j * 256;
            int r = idx >> 2, q = idx & 3;
            const void* s = src + (size_t)r * K + k0 + q * 8;
            uint32_t d = sbase + b * BUF_B + r * 80 + q * 16;
            asm volatile("cp.async.cg.shared.global [%0], [%1], 16;"
                         :: "r"(d), "l"(s) : "memory");
        }
    }
}

__global__ void __launch_bounds__(256)
gemm_mma(const __nv_bfloat16* __restrict__ Ahi, const __nv_bfloat16* __restrict__ Alo,
         const __nv_bfloat16* __restrict__ Bhi, const __nv_bfloat16* __restrict__ Blo,
         float* __restrict__ C, int M, int N, int K)
{
    extern __shared__ char smraw[];
    const uint32_t sb = smem_u32(smraw);

    const int tid  = threadIdx.x;
    const int wid  = tid >> 5;
    const int lane = tid & 31;
    const int wm   = wid >> 2;      // 0..1
    const int wn   = wid & 3;       // 0..3
    const int m0   = blockIdx.y << 7;
    const int n0   = blockIdx.x << 7;

    const __nv_bfloat16* pA0 = Ahi + (size_t)m0 * K;
    const __nv_bfloat16* pA1 = Alo + (size_t)m0 * K;
    const __nv_bfloat16* pB0 = Bhi + (size_t)n0 * K;
    const __nv_bfloat16* pB1 = Blo + (size_t)n0 * K;

    float c[4][4][4];
#pragma unroll
    for (int a = 0; a < 4; a++)
#pragma unroll
        for (int b = 0; b < 4; b++)
#pragma unroll
            for (int d = 0; d < 4; d++) c[a][b][d] = 0.f;

    // ldmatrix per-thread address components
    const int a_roff = (lane & 7) + ((lane >> 3) & 1) * 8;   // m within tile
    const int a_koff = ((lane >> 4) & 1) * 8;                // k within 16
    const int b_roff = (lane & 7) + ((lane >> 4) & 1) * 8;   // n within 16
    const int b_koff = ((lane >> 3) & 1) * 8;

    const int nch = K >> 5;   // K / 32

    g2s_chunk(sb, pA0, pA1, pB0, pB1, K, 0, tid);
    asm volatile("cp.async.commit_group;" ::: "memory");

    for (int i = 0; i < nch; i++) {
        if (i + 1 < nch) {
            g2s_chunk(sb + ((i + 1) & 1) * STG_B, pA0, pA1, pB0, pB1,
                      K, (i + 1) << 5, tid);
            asm volatile("cp.async.commit_group;" ::: "memory");
            asm volatile("cp.async.wait_group 1;" ::: "memory");
        } else {
            asm volatile("cp.async.wait_group 0;" ::: "memory");
        }
        __syncthreads();

        const uint32_t st   = sb + (i & 1) * STG_B;
        const uint32_t sAh  = st +            (wm * 64 + a_roff) * 80 + a_koff * 2;
        const uint32_t sAl  = sAh + BUF_B;
        const uint32_t sBh  = st + 2 * BUF_B + (wn * 32 + b_roff) * 80 + b_koff * 2;
        const uint32_t sBl  = sBh + BUF_B;

#pragma unroll
        for (int ks = 0; ks < 2; ks++) {
            const int kb = ks * 32;   // 16 bf16 * 2B
            uint32_t ah[4][4], al[4][4], bh[2][4], bl[2][4];
#pragma unroll
            for (int mi = 0; mi < 4; mi++) ldm4(ah[mi], sAh + mi * 16 * 80 + kb);
#pragma unroll
            for (int np = 0; np < 2; np++) ldm4(bh[np], sBh + np * 16 * 80 + kb);
#pragma unroll
            for (int mi = 0; mi < 4; mi++) ldm4(al[mi], sAl + mi * 16 * 80 + kb);
#pragma unroll
            for (int np = 0; np < 2; np++) ldm4(bl[np], sBl + np * 16 * 80 + kb);

#pragma unroll
            for (int mi = 0; mi < 4; mi++)
#pragma unroll
                for (int np = 0; np < 2; np++) {
                    // hi*hi
                    mma16816(c[mi][np * 2],     ah[mi], bh[np][0], bh[np][1]);
                    mma16816(c[mi][np * 2 + 1], ah[mi], bh[np][2], bh[np][3]);
                    // hi*lo
                    mma16816(c[mi][np * 2],     ah[mi], bl[np][0], bl[np][1]);
                    mma16816(c[mi][np * 2 + 1], ah[mi], bl[np][2], bl[np][3]);
                    // lo*hi
                    mma16816(c[mi][np * 2],     al[mi], bh[np][0], bh[np][1]);
                    mma16816(c[mi][np * 2 + 1], al[mi], bh[np][2], bh[np][3]);
                }
        }
        __syncthreads();
    }

    // epilogue
    const int g  = lane >> 2;
    const int i2 = (lane & 3) * 2;
#pragma unroll
    for (int mi = 0; mi < 4; mi++)
#pragma unroll
        for (int ni = 0; ni < 4; ni++) {
            float* p = C + (size_t)(m0 + wm * 64 + mi * 16 + g) * N
                         + n0 + wn * 32 + ni * 8 + i2;
            *(float2*)p           = make_float2(c[mi][ni][0], c[mi][ni][1]);
            *(float2*)(p + 8 * N) = make_float2(c[mi][ni][2], c[mi][ni][3]);
        }
}

// ===================================================================
// RoPE in-place
// ===================================================================
__global__ void rope_kernel(float* __restrict__ X,
                            const float* __restrict__ cs,
                            const float* __restrict__ sn,
                            int heads, int total)
{
    int idx = blockIdx.x * blockDim.x + threadIdx.x;
    if (idx >= total) return;
    int d   = idx & 31;
    int hh  = (idx >> 5) % heads;
    int row = idx / (heads * 32);

    float c1 = cs[row * 64 + d];
    float s1 = sn[row * 64 + d];
    float c2 = cs[row * 64 + d + 32];
    float s2 = sn[row * 64 + d + 32];

    float* p = X + (size_t)row * heads * 64 + hh * 64;
    float x1 = p[d], x2 = p[d + 32];
    p[d]      = x1 * c1 - x2 * s1;
    p[d + 32] = x2 * c2 + x1 * s2;
}

// ===================================================================
// Flash attention fp32, causal, GQA (unchanged; passed R2)
// ===================================================================
#define LDS_ 68

__global__ void __launch_bounds__(256)
flash_kernel(const float* __restrict__ Qg, const float* __restrict__ Kg,
             const float* __restrict__ Vg, float* __restrict__ Og)
{
    extern __shared__ float sm[];
    float* Qs  = sm;
    float* KPs = sm + 64 * LDS_;
    float* Vs  = sm + 2 * 64 * LDS_;

    const int qt  = blockIdx.x;
    const int h   = blockIdx.y;
    const int b   = blockIdx.z;
    const int kvh = h >> 2;

    const int tid = threadIdx.x;
    const int tx  = tid & 15;
    const int ty  = tid >> 4;
    const int R0  = ty * 4;
    const int C0  = tx * 4;

    const int lrow  = tid >> 4;
    const int lquad = tid & 15;

    {
        const float* src = Qg + ((size_t)(b * SEQ + qt * 64)) * (NH * HDIM) + h * HDIM;
#pragma unroll
        for (int p = 0; p < 4; p++) {
            int row = p * 16 + lrow;
            float4 v = *(const float4*)(src + (size_t)row * (NH * HDIM) + lquad * 4);
            v.x *= QK_SCALE; v.y *= QK_SCALE; v.z *= QK_SCALE; v.w *= QK_SCALE;
            *(float4*)&Qs[row * LDS_ + lquad * 4] = v;
        }
    }

    float m_r[4], l_r[4], o[4][4];
#pragma unroll
    for (int r = 0; r < 4; r++) {
        m_r[r] = -1e30f;
        l_r[r] = 0.f;
#pragma unroll
        for (int c = 0; c < 4; c++) o[r][c] = 0.f;
    }

    const float* ksrc = Kg + ((size_t)(b * SEQ)) * (NKVH * HDIM) + kvh * HDIM;
    const float* vsrc = Vg + ((size_t)(b * SEQ)) * (NKVH * HDIM) + kvh * HDIM;

    for (int j = 0; j <= qt; j++) {
        __syncthreads();
#pragma unroll
        for (int p = 0; p < 4; p++) {
            int row = p * 16 + lrow;
            *(float4*)&KPs[row * LDS_ + lquad * 4] =
                *(const float4*)(ksrc + (size_t)(j * 64 + row) * (NKVH * HDIM) + lquad * 4);
            *(float4*)&Vs[row * LDS_ + lquad * 4] =
                *(const float4*)(vsrc + (size_t)(j * 64 + row) * (NKVH * HDIM) + lquad * 4);
        }
        __syncthreads();

        float s[4][4];
#pragma unroll
        for (int r = 0; r < 4; r++)
#pragma unroll
            for (int c = 0; c < 4; c++) s[r][c] = 0.f;

#pragma unroll
        for (int d = 0; d < 64; d += 4) {
            float4 q4[4], k4[4];
#pragma unroll
            for (int r = 0; r < 4; r++) q4[r] = *(float4*)&Qs[(R0 + r) * LDS_ + d];
#pragma unroll
            for (int c = 0; c < 4; c++) k4[c] = *(float4*)&KPs[(C0 + c) * LDS_ + d];
#pragma unroll
            for (int r = 0; r < 4; r++)
#pragma unroll
                for (int c = 0; c < 4; c++)
                    s[r][c] += q4[r].x * k4[c].x + q4[r].y * k4[c].y +
                               q4[r].z * k4[c].z + q4[r].w * k4[c].w;
        }

        if (j == qt) {
#pragma unroll
            for (int r = 0; r < 4; r++)
#pragma unroll
                for (int c = 0; c < 4; c++)
                    if (C0 + c > R0 + r) s[r][c] = -1e30f;
        }

#pragma unroll
        for (int r = 0; r < 4; r++) {
            float mx = fmaxf(fmaxf(s[r][0], s[r][1]), fmaxf(s[r][2], s[r][3]));
#pragma unroll
            for (int off = 8; off; off >>= 1)
                mx = fmaxf(mx, __shfl_xor_sync(0xffffffffu, mx, off));
            float mnew  = fmaxf(m_r[r], mx);
            float alpha = __expf(m_r[r] - mnew);
            float sum = 0.f;
#pragma unroll
            for (int c = 0; c < 4; c++) {
                float e = __expf(s[r][c] - mnew);
                s[r][c] = e;
                sum += e;
            }
#pragma unroll
            for (int off = 8; off; off >>= 1)
                sum += __shfl_xor_sync(0xffffffffu, sum, off);
            l_r[r] = l_r[r] * alpha + sum;
            m_r[r] = mnew;
#pragma unroll
            for (int c = 0; c < 4; c++) o[r][c] *= alpha;
        }

        __syncthreads();
#pragma unroll
        for (int r = 0; r < 4; r++)
            *(float4*)&KPs[(R0 + r) * LDS_ + C0] =
                make_float4(s[r][0], s[r][1], s[r][2], s[r][3]);
        __syncthreads();

#pragma unroll
        for (int c0 = 0; c0 < 64; c0 += 4) {
            float4 p4[4], v4[4];
#pragma unroll
            for (int r = 0; r < 4; r++) p4[r] = *(float4*)&KPs[(R0 + r) * LDS_ + c0];
#pragma unroll
            for (int i = 0; i < 4; i++) v4[i] = *(float4*)&Vs[(c0 + i) * LDS_ + C0];
#pragma unroll
            for (int r = 0; r < 4; r++) {
                o[r][0] += p4[r].x * v4[0].x + p4[r].y * v4[1].x + p4[r].z * v4[2].x + p4[r].w * v4[3].x;
                o[r][1] += p4[r].x * v4[0].y + p4[r].y * v4[1].y + p4[r].z * v4[2].y + p4[r].w * v4[3].y;
                o[r][2] += p4[r].x * v4[0].z + p4[r].y * v4[1].z + p4[r].z * v4[2].z + p4[r].w * v4[3].z;
                o[r][3] += p4[r].x * v4[0].w + p4[r].y * v4[1].w + p4[r].z * v4[2].w + p4[r].w * v4[3].w;
            }
        }
    }

    float* dst = Og + ((size_t)(b * SEQ + qt * 64)) * (NH * HDIM) + h * HDIM;
#pragma unroll
    for (int r = 0; r < 4; r++) {
        float inv = 1.0f / l_r[r];
        float4 v = make_float4(o[r][0] * inv, o[r][1] * inv, o[r][2] * inv, o[r][3] * inv);
        *(float4*)(dst + (size_t)(R0 + r) * (NH * HDIM) + C0) = v;
    }
}

// ===================================================================
// Launch: 0 hidden, 1 cos, 2 sin, 3 mask (unused), 4 Wq, 5 Wk, 6 Wv, 7 Wo
// ===================================================================
extern "C" void kernel_launch(void* const* d_in, const int* in_sizes, int n_in,
                              void* d_out, int out_size)
{
    const float* hs = (const float*)d_in[0];
    const float* cs = (const float*)d_in[1];
    const float* sn = (const float*)d_in[2];
    const float* Wq = (const float*)d_in[4];
    const float* Wk = (const float*)d_in[5];
    const float* Wv = (const float*)d_in[6];
    const float* Wo = (const float*)d_in[7];
    float* out = (float*)d_out;

    float *Qb, *Kb, *Vb, *Ob;
    __nv_bfloat16 *aHi, *aLo, *wHi, *wLo;
    cudaGetSymbolAddress((void**)&Qb, g_Q);
    cudaGetSymbolAddress((void**)&Kb, g_K);
    cudaGetSymbolAddress((void**)&Vb, g_V);
    cudaGetSymbolAddress((void**)&Ob, g_O);
    cudaGetSymbolAddress((void**)&aHi, g_act_hi);
    cudaGetSymbolAddress((void**)&aLo, g_act_lo);
    cudaGetSymbolAddress((void**)&wHi, g_w_hi);
    cudaGetSymbolAddress((void**)&wLo, g_w_lo);

    cudaFuncSetAttribute(gemm_mma, cudaFuncAttributeMaxDynamicSharedMemorySize, GEMM_SMEM);

    const int actN4 = MROWS * DMODEL / 4;
    const int wBig4 = DMODEL * DMODEL / 4;
    const int wKV4  = (NKVH * HDIM) * DMODEL / 4;

    // activations -> bf16 hi/lo
    split_bf16x2<<<(actN4 + 255) / 256, 256>>>(hs, aHi, aLo, actN4);

    // Q projection
    split_bf16x2<<<(wBig4 + 255) / 256, 256>>>(Wq, wHi, wLo, wBig4);
    gemm_mma<<<dim3((NH * HDIM) / 128, MROWS / 128), 256, GEMM_SMEM>>>(
        aHi, aLo, wHi, wLo, Qb, MROWS, NH * HDIM, DMODEL);

    // K projection
    split_bf16x2<<<(wKV4 + 255) / 256, 256>>>(Wk, wHi, wLo, wKV4);
    gemm_mma<<<dim3((NKVH * HDIM) / 128, MROWS / 128), 256, GEMM_SMEM>>>(
        aHi, aLo, wHi, wLo, Kb, MROWS, NKVH * HDIM, DMODEL);

    // V projection
    split_bf16x2<<<(wKV4 + 255) / 256, 256>>>(Wv, wHi, wLo, wKV4);
    gemm_mma<<<dim3((NKVH * HDIM) / 128, MROWS / 128), 256, GEMM_SMEM>>>(
        aHi, aLo, wHi, wLo, Vb, MROWS, NKVH * HDIM, DMODEL);

    // RoPE
    {
        int totalQ = MROWS * NH * 32;
        rope_kernel<<<(totalQ + 255) / 256, 256>>>(Qb, cs, sn, NH, totalQ);
        int totalK = MROWS * NKVH * 32;
        rope_kernel<<<(totalK + 255) / 256, 256>>>(Kb, cs, sn, NKVH, totalK);
    }

    // Attention
    const int flash_smem = 3 * 64 * LDS_ * (int)sizeof(float);
    cudaFuncSetAttribute(flash_kernel, cudaFuncAttributeMaxDynamicSharedMemorySize, flash_smem);
    flash_kernel<<<dim3(SEQ / 64, NH, BSZ), 256, flash_smem>>>(Qb, Kb, Vb, Ob);

    // Output projection
    split_bf16x2<<<(actN4 + 255) / 256, 256>>>(Ob, aHi, aLo, actN4);
    split_bf16x2<<<(wBig4 + 255) / 256, 256>>>(Wo, wHi, wLo, wBig4);
    gemm_mma<<<dim3(DMODEL / 128, MROWS / 128), 256, GEMM_SMEM>>>(
        aHi, aLo, wHi, wLo, out, MROWS, DMODEL, DMODEL);
}

// round 7
// speedup vs baseline: 2.8838x; 1.9445x over previous
#include <cuda_runtime.h>
#include <cuda_bf16.h>
#include <cstdint>

// Problem constants
#define BSZ   2
#define SEQ   2048
#define DMODEL 2048
#define NH    32
#define NKVH  8
#define HDIM  64
#define QK_SCALE 0.125f
#define MROWS (BSZ*SEQ)   // 4096

// -------- scratch (static device globals: allocation-free) --------
__device__ float g_Q[(size_t)MROWS * NH * HDIM];     // 32 MB
__device__ float g_K[(size_t)MROWS * NKVH * HDIM];   //  8 MB
__device__ float g_V[(size_t)MROWS * NKVH * HDIM];   //  8 MB
__device__ float g_O[(size_t)MROWS * NH * HDIM];     // 32 MB
__device__ __nv_bfloat16 g_act_hi[(size_t)MROWS * DMODEL];   // also Q hi for flash
__device__ __nv_bfloat16 g_act_lo[(size_t)MROWS * DMODEL];   // also Q lo
__device__ __nv_bfloat16 g_w_hi[(size_t)DMODEL * DMODEL];
__device__ __nv_bfloat16 g_w_lo[(size_t)DMODEL * DMODEL];
__device__ __nv_bfloat16 g_kh[(size_t)BSZ * NKVH * SEQ * HDIM];
__device__ __nv_bfloat16 g_kl[(size_t)BSZ * NKVH * SEQ * HDIM];
__device__ __nv_bfloat16 g_vh[(size_t)BSZ * NKVH * SEQ * HDIM];
__device__ __nv_bfloat16 g_vl[(size_t)BSZ * NKVH * SEQ * HDIM];

// ===================================================================
// Helpers (base sm_103-safe: cp.async / ldmatrix / mma.sync only)
// ===================================================================
__device__ __forceinline__ uint32_t smem_u32(const void* p) {
    uint32_t a;
    asm("{ .reg .u64 t; cvta.to.shared.u64 t, %1; cvt.u32.u64 %0, t; }" : "=r"(a) : "l"(p));
    return a;
}
__device__ __forceinline__ void ldm4(uint32_t* r, uint32_t addr) {
    asm volatile("ldmatrix.sync.aligned.m8n8.x4.shared.b16 {%0,%1,%2,%3}, [%4];"
                 : "=r"(r[0]), "=r"(r[1]), "=r"(r[2]), "=r"(r[3]) : "r"(addr));
}
__device__ __forceinline__ void ldm4t(uint32_t* r, uint32_t addr) {
    asm volatile("ldmatrix.sync.aligned.m8n8.x4.trans.shared.b16 {%0,%1,%2,%3}, [%4];"
                 : "=r"(r[0]), "=r"(r[1]), "=r"(r[2]), "=r"(r[3]) : "r"(addr));
}
__device__ __forceinline__ void mma16816(float* c, const uint32_t* a,
                                         uint32_t b0, uint32_t b1) {
    asm volatile(
        "mma.sync.aligned.m16n8k16.row.col.f32.bf16.bf16.f32 "
        "{%0,%1,%2,%3}, {%4,%5,%6,%7}, {%8,%9}, {%0,%1,%2,%3};"
        : "+f"(c[0]), "+f"(c[1]), "+f"(c[2]), "+f"(c[3])
        : "r"(a[0]), "r"(a[1]), "r"(a[2]), "r"(a[3]), "r"(b0), "r"(b1));
}
__device__ __forceinline__ void cpa16(uint32_t d, const void* s) {
    asm volatile("cp.async.cg.shared.global [%0], [%1], 16;" :: "r"(d), "l"(s) : "memory");
}
// Fast exp on the FMA pipe (no MUFU). Valid for x <= ~80; clamped below.
__device__ __forceinline__ float fexp(float x) {
    float y = fmaxf(x, -87.0f) * 1.4426950408889634f;
    int   n = __float2int_rn(y);
    float f = y - (float)n;
    float p = 1.3333558146e-3f;
    p = fmaf(p, f, 9.6181291081e-3f);
    p = fmaf(p, f, 5.5504108664e-2f);
    p = fmaf(p, f, 2.4022650696e-1f);
    p = fmaf(p, f, 6.9314718056e-1f);
    p = fmaf(p, f, 1.0f);
    return __int_as_float((n + 127) << 23) * p;
}

// ===================================================================
// Split fp32 -> bf16 hi + bf16 lo (elementwise, float4 vectorized)
// ===================================================================
__global__ void split_bf16x2(const float* __restrict__ x,
                             __nv_bfloat16* __restrict__ hi,
                             __nv_bfloat16* __restrict__ lo, int n4)
{
    int i = blockIdx.x * blockDim.x + threadIdx.x;
    if (i >= n4) return;
    float4 v = ((const float4*)x)[i];
    __nv_bfloat16 h0 = __float2bfloat16(v.x);
    __nv_bfloat16 h1 = __float2bfloat16(v.y);
    __nv_bfloat16 h2 = __float2bfloat16(v.z);
    __nv_bfloat16 h3 = __float2bfloat16(v.w);
    __nv_bfloat16 l0 = __float2bfloat16(v.x - __bfloat162float(h0));
    __nv_bfloat16 l1 = __float2bfloat16(v.y - __bfloat162float(h1));
    __nv_bfloat16 l2 = __float2bfloat16(v.z - __bfloat162float(h2));
    __nv_bfloat16 l3 = __float2bfloat16(v.w - __bfloat162float(h3));
    __nv_bfloat162* H = (__nv_bfloat162*)hi;
    __nv_bfloat162* L = (__nv_bfloat162*)lo;
    __nv_bfloat162 p;
    p.x = h0; p.y = h1; H[2 * i] = p;
    p.x = h2; p.y = h3; H[2 * i + 1] = p;
    p.x = l0; p.y = l1; L[2 * i] = p;
    p.x = l2; p.y = l3; L[2 * i + 1] = p;
}

// ===================================================================
// Split-bf16 NT GEMM on mma.sync (validated R4)
// ===================================================================
#define BUF_B  10240
#define STG_B  (4 * BUF_B)
#define GEMM_SMEM (2 * STG_B)

__device__ __forceinline__ void g2s_chunk(uint32_t sbase,
    const __nv_bfloat16* __restrict__ A0, const __nv_bfloat16* __restrict__ A1,
    const __nv_bfloat16* __restrict__ B0, const __nv_bfloat16* __restrict__ B1,
    int K, int k0, int tid)
{
#pragma unroll
    for (int b = 0; b < 4; b++) {
        const __nv_bfloat16* src =
            (b == 0) ? A0 : (b == 1) ? A1 : (b == 2) ? B0 : B1;
#pragma unroll
        for (int j = 0; j < 2; j++) {
            int idx = tid + j * 256;
            int r = idx >> 2, q = idx & 3;
            cpa16(sbase + b * BUF_B + r * 80 + q * 16,
                  src + (size_t)r * K + k0 + q * 8);
        }
    }
}

__global__ void __launch_bounds__(256)
gemm_mma(const __nv_bfloat16* __restrict__ Ahi, const __nv_bfloat16* __restrict__ Alo,
         const __nv_bfloat16* __restrict__ Bhi, const __nv_bfloat16* __restrict__ Blo,
         float* __restrict__ C, int M, int N, int K)
{
    extern __shared__ char smraw[];
    const uint32_t sb = smem_u32(smraw);

    const int tid  = threadIdx.x;
    const int wid  = tid >> 5;
    const int lane = tid & 31;
    const int wm   = wid >> 2;
    const int wn   = wid & 3;
    const int m0   = blockIdx.y << 7;
    const int n0   = blockIdx.x << 7;

    const __nv_bfloat16* pA0 = Ahi + (size_t)m0 * K;
    const __nv_bfloat16* pA1 = Alo + (size_t)m0 * K;
    const __nv_bfloat16* pB0 = Bhi + (size_t)n0 * K;
    const __nv_bfloat16* pB1 = Blo + (size_t)n0 * K;

    float c[4][4][4];
#pragma unroll
    for (int a = 0; a < 4; a++)
#pragma unroll
        for (int b = 0; b < 4; b++)
#pragma unroll
            for (int d = 0; d < 4; d++) c[a][b][d] = 0.f;

    const int a_roff = (lane & 7) + ((lane >> 3) & 1) * 8;
    const int a_koff = ((lane >> 4) & 1) * 8;
    const int b_roff = (lane & 7) + ((lane >> 4) & 1) * 8;
    const int b_koff = ((lane >> 3) & 1) * 8;

    const int nch = K >> 5;

    g2s_chunk(sb, pA0, pA1, pB0, pB1, K, 0, tid);
    asm volatile("cp.async.commit_group;" ::: "memory");

    for (int i = 0; i < nch; i++) {
        if (i + 1 < nch) {
            g2s_chunk(sb + ((i + 1) & 1) * STG_B, pA0, pA1, pB0, pB1,
                      K, (i + 1) << 5, tid);
            asm volatile("cp.async.commit_group;" ::: "memory");
            asm volatile("cp.async.wait_group 1;" ::: "memory");
        } else {
            asm volatile("cp.async.wait_group 0;" ::: "memory");
        }
        __syncthreads();

        const uint32_t st   = sb + (i & 1) * STG_B;
        const uint32_t sAh  = st +            (wm * 64 + a_roff) * 80 + a_koff * 2;
        const uint32_t sAl  = sAh + BUF_B;
        const uint32_t sBh  = st + 2 * BUF_B + (wn * 32 + b_roff) * 80 + b_koff * 2;
        const uint32_t sBl  = sBh + BUF_B;

#pragma unroll
        for (int ks = 0; ks < 2; ks++) {
            const int kb = ks * 32;
            uint32_t ah[4][4], al[4][4], bh[2][4], bl[2][4];
#pragma unroll
            for (int mi = 0; mi < 4; mi++) ldm4(ah[mi], sAh + mi * 16 * 80 + kb);
#pragma unroll
            for (int np = 0; np < 2; np++) ldm4(bh[np], sBh + np * 16 * 80 + kb);
#pragma unroll
            for (int mi = 0; mi < 4; mi++) ldm4(al[mi], sAl + mi * 16 * 80 + kb);
#pragma unroll
            for (int np = 0; np < 2; np++) ldm4(bl[np], sBl + np * 16 * 80 + kb);

#pragma unroll
            for (int mi = 0; mi < 4; mi++)
#pragma unroll
                for (int np = 0; np < 2; np++) {
                    mma16816(c[mi][np * 2],     ah[mi], bh[np][0], bh[np][1]);
                    mma16816(c[mi][np * 2 + 1], ah[mi], bh[np][2], bh[np][3]);
                    mma16816(c[mi][np * 2],     ah[mi], bl[np][0], bl[np][1]);
                    mma16816(c[mi][np * 2 + 1], ah[mi], bl[np][2], bl[np][3]);
                    mma16816(c[mi][np * 2],     al[mi], bh[np][0], bh[np][1]);
                    mma16816(c[mi][np * 2 + 1], al[mi], bh[np][2], bh[np][3]);
                }
        }
        __syncthreads();
    }

    const int g  = lane >> 2;
    const int i2 = (lane & 3) * 2;
#pragma unroll
    for (int mi = 0; mi < 4; mi++)
#pragma unroll
        for (int ni = 0; ni < 4; ni++) {
            float* p = C + (size_t)(m0 + wm * 64 + mi * 16 + g) * N
                         + n0 + wn * 32 + ni * 8 + i2;
            *(float2*)p           = make_float2(c[mi][ni][0], c[mi][ni][1]);
            *(float2*)(p + 8 * N) = make_float2(c[mi][ni][2], c[mi][ni][3]);
        }
}

// ===================================================================
// RoPE + split to bf16 hi/lo, transposed to [B, heads, S, 64]
// ===================================================================
__global__ void rope_split(const float* __restrict__ X,     // [B*S, heads*64]
                           const float* __restrict__ cs, const float* __restrict__ sn,
                           __nv_bfloat16* __restrict__ Xhi,
                           __nv_bfloat16* __restrict__ Xlo,
                           int heads, float scale, int total)
{
    int idx = blockIdx.x * blockDim.x + threadIdx.x;
    if (idx >= total) return;
    int d   = idx & 31;
    int hh  = (idx >> 5) % heads;
    int row = idx / (heads * 32);

    float c1 = cs[row * 64 + d],      s1 = sn[row * 64 + d];
    float c2 = cs[row * 64 + d + 32], s2 = sn[row * 64 + d + 32];
    const float* p = X + (size_t)row * heads * 64 + hh * 64;
    float x1 = p[d], x2 = p[d + 32];
    float y1 = (x1 * c1 - x2 * s1) * scale;
    float y2 = (x2 * c2 + x1 * s2) * scale;

    int bb = row / SEQ, ss = row % SEQ;
    size_t o = ((size_t)(bb * heads + hh) * SEQ + ss) * 64;
    __nv_bfloat16 h1 = __float2bfloat16(y1);
    Xhi[o + d]      = h1;
    Xlo[o + d]      = __float2bfloat16(y1 - __bfloat162float(h1));
    __nv_bfloat16 h2 = __float2bfloat16(y2);
    Xhi[o + d + 32] = h2;
    Xlo[o + d + 32] = __float2bfloat16(y2 - __bfloat162float(h2));
}

// V: split + transpose only
__global__ void split_v(const float* __restrict__ X,   // [B*S, KVH*64]
                        __nv_bfloat16* __restrict__ Vhi,
                        __nv_bfloat16* __restrict__ Vlo, int total4)
{
    int idx = blockIdx.x * blockDim.x + threadIdx.x;
    if (idx >= total4) return;
    int d4  = idx & 15;
    int kvh = (idx >> 4) & (NKVH - 1);
    int row = idx >> 7;
    float4 v = *(const float4*)(X + (size_t)row * NKVH * 64 + kvh * 64 + d4 * 4);
    int bb = row / SEQ, ss = row % SEQ;
    size_t o = ((size_t)(bb * NKVH + kvh) * SEQ + ss) * 64 + d4 * 4;
    __nv_bfloat16 h0 = __float2bfloat16(v.x), h1 = __float2bfloat16(v.y);
    __nv_bfloat16 h2 = __float2bfloat16(v.z), h3 = __float2bfloat16(v.w);
    __nv_bfloat162 a, b;
    a.x = h0; a.y = h1; b.x = h2; b.y = h3;
    *(__nv_bfloat162*)(Vhi + o)     = a;
    *(__nv_bfloat162*)(Vhi + o + 2) = b;
    a.x = __float2bfloat16(v.x - __bfloat162float(h0));
    a.y = __float2bfloat16(v.y - __bfloat162float(h1));
    b.x = __float2bfloat16(v.z - __bfloat162float(h2));
    b.y = __float2bfloat16(v.w - __bfloat162float(h3));
    *(__nv_bfloat162*)(Vlo + o)     = a;
    *(__nv_bfloat162*)(Vlo + o + 2) = b;
}

// ===================================================================
// Flash attention v2: split-bf16 mma QK^T and PV, FMA-pipe exp.
// CTA: 64 q-rows x 64 kv, 4 warps (warp = 16 rows). Double-buffered KV.
// ===================================================================
#define FROWB 144
#define FTILE (64 * FROWB)       // 9216 B
#define FL_SMEM (10 * FTILE)     // 92160 B

__device__ __forceinline__ void fl_g2s_kv(uint32_t sb, int stage, int j,
    const __nv_bfloat16* kh, const __nv_bfloat16* kl,
    const __nv_bfloat16* vh, const __nv_bfloat16* vl, int tid)
{
#pragma unroll
    for (int t = 0; t < 16; t++) {
        int id  = tid + t * 128;
        int mat = id >> 9, rem = id & 511, r = rem >> 3, q = rem & 7;
        const __nv_bfloat16* base = (mat == 0) ? kh : (mat == 1) ? kl
                                  : (mat == 2) ? vh : vl;
        cpa16(sb + (2 + stage * 4 + mat) * FTILE + r * FROWB + q * 16,
              base + (size_t)(j * 64 + r) * 64 + q * 8);
    }
}

__global__ void __launch_bounds__(128)
flash2(const __nv_bfloat16* __restrict__ Qh, const __nv_bfloat16* __restrict__ Ql,
       const __nv_bfloat16* __restrict__ Kh, const __nv_bfloat16* __restrict__ Kl,
       const __nv_bfloat16* __restrict__ Vh, const __nv_bfloat16* __restrict__ Vl,
       float* __restrict__ Og)
{
    extern __shared__ char smraw[];
    const uint32_t sb = smem_u32(smraw);
    const int qt  = (int)gridDim.x - 1 - (int)blockIdx.x;  // heavy tiles first
    const int h   = blockIdx.y, b = blockIdx.z;
    const int kvh = h >> 2;
    const int tid = threadIdx.x, wid = tid >> 5, lane = tid & 31;

    const size_t qoff = ((size_t)(b * NH + h) * SEQ + (size_t)qt * 64) * 64;
    const size_t kvo  = (size_t)(b * NKVH + kvh) * SEQ * 64;
    const __nv_bfloat16* kh = Kh + kvo;
    const __nv_bfloat16* kl = Kl + kvo;
    const __nv_bfloat16* vh = Vh + kvo;
    const __nv_bfloat16* vl = Vl + kvo;

    // Q tiles (hi, lo) -> smem
#pragma unroll
    for (int t = 0; t < 8; t++) {
        int id  = tid + t * 128;
        int mat = id >> 9, rem = id & 511, r = rem >> 3, q = rem & 7;
        cpa16(sb + mat * FTILE + r * FROWB + q * 16,
              (mat ? Ql : Qh) + qoff + r * 64 + q * 8);
    }
    fl_g2s_kv(sb, 0, 0, kh, kl, vh, vl, tid);
    asm volatile("cp.async.commit_group;" ::: "memory");

    // fragment address components
    const int a_roff = (lane & 7) + ((lane >> 3) & 1) * 8;
    const int a_koff = ((lane >> 4) & 1) * 8;
    const int b_roff = (lane & 7) + ((lane >> 4) & 1) * 8;
    const int b_koff = ((lane >> 3) & 1) * 8;
    const int v_k    = (lane & 7) + ((lane >> 3) & 1) * 8;
    const int v_d    = ((lane >> 4) & 1) * 8;
    const uint32_t qa_h = sb + (wid * 16 + a_roff) * FROWB + a_koff * 2;
    const uint32_t qa_l = qa_h + FTILE;

    float o[8][4];
#pragma unroll
    for (int t = 0; t < 8; t++)
#pragma unroll
        for (int e = 0; e < 4; e++) o[t][e] = 0.f;
    float m0 = -1e30f, m1 = -1e30f, l0 = 0.f, l1 = 0.f;

    for (int j = 0; j <= qt; j++) {
        if (j < qt) {
            fl_g2s_kv(sb, (j + 1) & 1, j + 1, kh, kl, vh, vl, tid);
            asm volatile("cp.async.commit_group;" ::: "memory");
            asm volatile("cp.async.wait_group 1;" ::: "memory");
        } else {
            asm volatile("cp.async.wait_group 0;" ::: "memory");
        }
        __syncthreads();
        const uint32_t st = sb + (2 + (j & 1) * 4) * FTILE;

        // ---- S = Q K^T (3-pass split) ----
        float s[8][4];
#pragma unroll
        for (int t = 0; t < 8; t++)
#pragma unroll
            for (int e = 0; e < 4; e++) s[t][e] = 0.f;

#pragma unroll
        for (int ks = 0; ks < 4; ks++) {
            const uint32_t kb = ks * 32;
            uint32_t ah[4], al[4];
            ldm4(ah, qa_h + kb);
            ldm4(al, qa_l + kb);
#pragma unroll
            for (int ng = 0; ng < 4; ng++) {
                uint32_t kh4[4], kl4[4];
                uint32_t ka = st + (ng * 16 + b_roff) * FROWB + b_koff * 2 + kb;
                ldm4(kh4, ka);
                ldm4(kl4, ka + FTILE);
                mma16816(s[2 * ng],     ah, kh4[0], kh4[1]);
                mma16816(s[2 * ng + 1], ah, kh4[2], kh4[3]);
                mma16816(s[2 * ng],     ah, kl4[0], kl4[1]);
                mma16816(s[2 * ng + 1], ah, kl4[2], kl4[3]);
                mma16816(s[2 * ng],     al, kh4[0], kh4[1]);
                mma16816(s[2 * ng + 1], al, kh4[2], kh4[3]);
            }
        }

        // ---- causal mask on diagonal tile ----
        if (j == qt) {
            int r0 = wid * 16 + (lane >> 2);
#pragma unroll
            for (int t = 0; t < 8; t++) {
                int c = t * 8 + (lane & 3) * 2;
                if (c     > r0)     s[t][0] = -1e30f;
                if (c + 1 > r0)     s[t][1] = -1e30f;
                if (c     > r0 + 8) s[t][2] = -1e30f;
                if (c + 1 > r0 + 8) s[t][3] = -1e30f;
            }
        }

        // ---- online softmax (per-lane rows r, r+8) ----
        float mx0 = -1e30f, mx1 = -1e30f;
#pragma unroll
        for (int t = 0; t < 8; t++) {
            mx0 = fmaxf(mx0, fmaxf(s[t][0], s[t][1]));
            mx1 = fmaxf(mx1, fmaxf(s[t][2], s[t][3]));
        }
        mx0 = fmaxf(mx0, __shfl_xor_sync(0xffffffffu, mx0, 1));
        mx0 = fmaxf(mx0, __shfl_xor_sync(0xffffffffu, mx0, 2));
        mx1 = fmaxf(mx1, __shfl_xor_sync(0xffffffffu, mx1, 1));
        mx1 = fmaxf(mx1, __shfl_xor_sync(0xffffffffu, mx1, 2));
        float mn0 = fmaxf(m0, mx0), mn1 = fmaxf(m1, mx1);
        float al0 = fexp(m0 - mn0), al1 = fexp(m1 - mn1);
        m0 = mn0; m1 = mn1;
        float sum0 = 0.f, sum1 = 0.f;
#pragma unroll
        for (int t = 0; t < 8; t++) {
            s[t][0] = fexp(s[t][0] - mn0); sum0 += s[t][0];
            s[t][1] = fexp(s[t][1] - mn0); sum0 += s[t][1];
            s[t][2] = fexp(s[t][2] - mn1); sum1 += s[t][2];
            s[t][3] = fexp(s[t][3] - mn1); sum1 += s[t][3];
        }
        l0 = l0 * al0 + sum0;          // lane-partial; reduced at end
        l1 = l1 * al1 + sum1;
#pragma unroll
        for (int t = 0; t < 8; t++) {
            o[t][0] *= al0; o[t][1] *= al0;
            o[t][2] *= al1; o[t][3] *= al1;
        }

        // ---- O += P V (3-pass split, P from registers) ----
#pragma unroll
        for (int ks = 0; ks < 4; ks++) {
            uint32_t ph[4], pl[4];
#pragma unroll
            for (int half = 0; half < 2; half++) {
                const int t = 2 * ks + half;
#pragma unroll
                for (int rr = 0; rr < 2; rr++) {
                    float x0 = s[t][rr * 2], x1 = s[t][rr * 2 + 1];
                    __nv_bfloat16 h0 = __float2bfloat16(x0);
                    __nv_bfloat16 h1 = __float2bfloat16(x1);
                    __nv_bfloat162 H; H.x = h0; H.y = h1;
                    __nv_bfloat162 L;
                    L.x = __float2bfloat16(x0 - __bfloat162float(h0));
                    L.y = __float2bfloat16(x1 - __bfloat162float(h1));
                    ph[half * 2 + rr] = *(uint32_t*)&H;
                    pl[half * 2 + rr] = *(uint32_t*)&L;
                }
            }
#pragma unroll
            for (int dg = 0; dg < 4; dg++) {
                uint32_t vh4[4], vl4[4];
                uint32_t va = st + 2 * FTILE + (ks * 16 + v_k) * FROWB
                              + (dg * 16 + v_d) * 2;
                ldm4t(vh4, va);
                ldm4t(vl4, va + FTILE);
                mma16816(o[2 * dg],     ph, vh4[0], vh4[1]);
                mma16816(o[2 * dg + 1], ph, vh4[2], vh4[3]);
                mma16816(o[2 * dg],     ph, vl4[0], vl4[1]);
                mma16816(o[2 * dg + 1], ph, vl4[2], vl4[3]);
                mma16816(o[2 * dg],     pl, vh4[0], vh4[1]);
                mma16816(o[2 * dg + 1], pl, vh4[2], vh4[3]);
            }
        }
        __syncthreads();   // stage reuse safety for next prefetch
    }

    // ---- epilogue ----
    l0 += __shfl_xor_sync(0xffffffffu, l0, 1);
    l0 += __shfl_xor_sync(0xffffffffu, l0, 2);
    l1 += __shfl_xor_sync(0xffffffffu, l1, 1);
    l1 += __shfl_xor_sync(0xffffffffu, l1, 2);
    float inv0 = 1.f / l0, inv1 = 1.f / l1;

    int r0 = qt * 64 + wid * 16 + (lane >> 2);
    float* ob = Og + ((size_t)b * SEQ + r0) * DMODEL + h * 64 + (lane & 3) * 2;
#pragma unroll
    for (int t = 0; t < 8; t++) {
        *(float2*)(ob + t * 8) = make_float2(o[t][0] * inv0, o[t][1] * inv0);
        *(float2*)(ob + 8 * DMODEL + t * 8) = make_float2(o[t][2] * inv1, o[t][3] * inv1);
    }
}

// ===================================================================
// Launch: 0 hidden, 1 cos, 2 sin, 3 mask (unused), 4 Wq, 5 Wk, 6 Wv, 7 Wo
// ===================================================================
extern "C" void kernel_launch(void* const* d_in, const int* in_sizes, int n_in,
                              void* d_out, int out_size)
{
    const float* hs = (const float*)d_in[0];
    const float* cs = (const float*)d_in[1];
    const float* sn = (const float*)d_in[2];
    const float* Wq = (const float*)d_in[4];
    const float* Wk = (const float*)d_in[5];
    const float* Wv = (const float*)d_in[6];
    const float* Wo = (const float*)d_in[7];
    float* out = (float*)d_out;

    float *Qb, *Kb, *Vb, *Ob;
    __nv_bfloat16 *aHi, *aLo, *wHi, *wLo, *kh, *kl, *vh, *vl;
    cudaGetSymbolAddress((void**)&Qb, g_Q);
    cudaGetSymbolAddress((void**)&Kb, g_K);
    cudaGetSymbolAddress((void**)&Vb, g_V);
    cudaGetSymbolAddress((void**)&Ob, g_O);
    cudaGetSymbolAddress((void**)&aHi, g_act_hi);
    cudaGetSymbolAddress((void**)&aLo, g_act_lo);
    cudaGetSymbolAddress((void**)&wHi, g_w_hi);
    cudaGetSymbolAddress((void**)&wLo, g_w_lo);
    cudaGetSymbolAddress((void**)&kh, g_kh);
    cudaGetSymbolAddress((void**)&kl, g_kl);
    cudaGetSymbolAddress((void**)&vh, g_vh);
    cudaGetSymbolAddress((void**)&vl, g_vl);

    cudaFuncSetAttribute(gemm_mma, cudaFuncAttributeMaxDynamicSharedMemorySize, GEMM_SMEM);
    cudaFuncSetAttribute(flash2,   cudaFuncAttributeMaxDynamicSharedMemorySize, FL_SMEM);

    const int actN4 = MROWS * DMODEL / 4;
    const int wBig4 = DMODEL * DMODEL / 4;
    const int wKV4  = (NKVH * HDIM) * DMODEL / 4;

    // activations -> bf16 hi/lo
    split_bf16x2<<<(actN4 + 255) / 256, 256>>>(hs, aHi, aLo, actN4);

    // projections
    split_bf16x2<<<(wBig4 + 255) / 256, 256>>>(Wq, wHi, wLo, wBig4);
    gemm_mma<<<dim3((NH * HDIM) / 128, MROWS / 128), 256, GEMM_SMEM>>>(
        aHi, aLo, wHi, wLo, Qb, MROWS, NH * HDIM, DMODEL);
    split_bf16x2<<<(wKV4 + 255) / 256, 256>>>(Wk, wHi, wLo, wKV4);
    gemm_mma<<<dim3((NKVH * HDIM) / 128, MROWS / 128), 256, GEMM_SMEM>>>(
        aHi, aLo, wHi, wLo, Kb, MROWS, NKVH * HDIM, DMODEL);
    split_bf16x2<<<(wKV4 + 255) / 256, 256>>>(Wv, wHi, wLo, wKV4);
    gemm_mma<<<dim3((NKVH * HDIM) / 128, MROWS / 128), 256, GEMM_SMEM>>>(
        aHi, aLo, wHi, wLo, Vb, MROWS, NKVH * HDIM, DMODEL);

    // RoPE + split (Q reuses act buffers, safe stream-ordered)
    {
        int totalQ = MROWS * NH * 32;
        rope_split<<<(totalQ + 255) / 256, 256>>>(Qb, cs, sn, aHi, aLo,
                                                  NH, QK_SCALE, totalQ);
        int totalK = MROWS * NKVH * 32;
        rope_split<<<(totalK + 255) / 256, 256>>>(Kb, cs, sn, kh, kl,
                                                  NKVH, 1.0f, totalK);
        int totalV4 = MROWS * NKVH * 16;
        split_v<<<(totalV4 + 255) / 256, 256>>>(Vb, vh, vl, totalV4);
    }

    // attention
    flash2<<<dim3(SEQ / 64, NH, BSZ), 128, FL_SMEM>>>(aHi, aLo, kh, kl, vh, vl, Ob);

    // output projection
    split_bf16x2<<<(actN4 + 255) / 256, 256>>>(Ob, aHi, aLo, actN4);
    split_bf16x2<<<(wBig4 + 255) / 256, 256>>>(Wo, wHi, wLo, wBig4);
    gemm_mma<<<dim3(DMODEL / 128, MROWS / 128), 256, GEMM_SMEM>>>(
        aHi, aLo, wHi, wLo, out, MROWS, DMODEL, DMODEL);
}

// round 8
// speedup vs baseline: 4.7444x; 1.6451x over previous
#include <cuda_runtime.h>
#include <cuda_fp16.h>
#include <cstdint>

// Problem constants
#define BSZ   2
#define SEQ   2048
#define DMODEL 2048
#define NH    32
#define NKVH  8
#define HDIM  64
#define QK_SCALE 0.125f
#define MROWS (BSZ*SEQ)   // 4096
#define NQKV  3072        // 2048 Q + 512 K + 512 V

// -------- scratch (static device globals: allocation-free) --------
__device__ float  g_QKV[(size_t)MROWS * NQKV];            // 50.3 MB
__device__ __half g_ah[(size_t)MROWS * DMODEL];           // act hi / Q hi
__device__ __half g_al[(size_t)MROWS * DMODEL];           // act lo / Q lo
__device__ __half g_oh[(size_t)MROWS * DMODEL];           // O hi
__device__ __half g_ol[(size_t)MROWS * DMODEL];           // O lo
__device__ __half g_wh[(size_t)NQKV * DMODEL];            // weights fp16 (fused QKV / Wo)
__device__ __half g_kh[(size_t)BSZ * NKVH * SEQ * HDIM];  // K fp16
__device__ __half g_vh[(size_t)BSZ * NKVH * SEQ * HDIM];  // V fp16

// ===================================================================
// Helpers
// ===================================================================
__device__ __forceinline__ uint32_t smem_u32(const void* p) {
    uint32_t a;
    asm("{ .reg .u64 t; cvta.to.shared.u64 t, %1; cvt.u32.u64 %0, t; }" : "=r"(a) : "l"(p));
    return a;
}
__device__ __forceinline__ void ldm4(uint32_t* r, uint32_t addr) {
    asm volatile("ldmatrix.sync.aligned.m8n8.x4.shared.b16 {%0,%1,%2,%3}, [%4];"
                 : "=r"(r[0]), "=r"(r[1]), "=r"(r[2]), "=r"(r[3]) : "r"(addr));
}
__device__ __forceinline__ void ldm4t(uint32_t* r, uint32_t addr) {
    asm volatile("ldmatrix.sync.aligned.m8n8.x4.trans.shared.b16 {%0,%1,%2,%3}, [%4];"
                 : "=r"(r[0]), "=r"(r[1]), "=r"(r[2]), "=r"(r[3]) : "r"(addr));
}
__device__ __forceinline__ void mma16816(float* c, const uint32_t* a,
                                         uint32_t b0, uint32_t b1) {
    asm volatile(
        "mma.sync.aligned.m16n8k16.row.col.f32.f16.f16.f32 "
        "{%0,%1,%2,%3}, {%4,%5,%6,%7}, {%8,%9}, {%0,%1,%2,%3};"
        : "+f"(c[0]), "+f"(c[1]), "+f"(c[2]), "+f"(c[3])
        : "r"(a[0]), "r"(a[1]), "r"(a[2]), "r"(a[3]), "r"(b0), "r"(b1));
}
__device__ __forceinline__ void cpa16(uint32_t d, const void* s) {
    asm volatile("cp.async.cg.shared.global [%0], [%1], 16;" :: "r"(d), "l"(s) : "memory");
}
// Fast exp on the FMA pipe (no MUFU).
__device__ __forceinline__ float fexp(float x) {
    float y = fmaxf(x, -87.0f) * 1.4426950408889634f;
    int   n = __float2int_rn(y);
    float f = y - (float)n;
    float p = 1.3333558146e-3f;
    p = fmaf(p, f, 9.6181291081e-3f);
    p = fmaf(p, f, 5.5504108664e-2f);
    p = fmaf(p, f, 2.4022650696e-1f);
    p = fmaf(p, f, 6.9314718056e-1f);
    p = fmaf(p, f, 1.0f);
    return __int_as_float((n + 127) << 23) * p;
}

// ===================================================================
// fp32 -> fp16 hi + fp16 lo (activations; error-free split to ~22 bits)
// ===================================================================
__global__ void split_fp16x2(const float* __restrict__ x,
                             __half* __restrict__ hi, __half* __restrict__ lo, int n4)
{
    int i = blockIdx.x * blockDim.x + threadIdx.x;
    if (i >= n4) return;
    float4 v = ((const float4*)x)[i];
    __half h0 = __float2half_rn(v.x), h1 = __float2half_rn(v.y);
    __half h2 = __float2half_rn(v.z), h3 = __float2half_rn(v.w);
    __half2* H = (__half2*)hi;
    __half2* L = (__half2*)lo;
    H[2 * i]     = __halves2half2(h0, h1);
    H[2 * i + 1] = __halves2half2(h2, h3);
    L[2 * i]     = __halves2half2(__float2half_rn(v.x - __half2float(h0)),
                                  __float2half_rn(v.y - __half2float(h1)));
    L[2 * i + 1] = __halves2half2(__float2half_rn(v.z - __half2float(h2)),
                                  __float2half_rn(v.w - __half2float(h3)));
}

// fp32 -> fp16 single (weights, V)
__global__ void conv_fp16(const float* __restrict__ x, __half* __restrict__ y, int n4)
{
    int i = blockIdx.x * blockDim.x + threadIdx.x;
    if (i >= n4) return;
    float4 v = ((const float4*)x)[i];
    __half2* Y = (__half2*)y;
    Y[2 * i]     = __halves2half2(__float2half_rn(v.x), __float2half_rn(v.y));
    Y[2 * i + 1] = __halves2half2(__float2half_rn(v.z), __float2half_rn(v.w));
}

// ===================================================================
// 2-pass fp16 NT GEMM: C[M,N] = (Ahi+Alo)[M,K] @ W[N,K]^T, fp32 acc
// CTA 128x128, k-chunk 32, 8 warps (2m x 4n), warp tile 64x32.
// ===================================================================
#define BUF_B  10240            // 128 rows * 80 B
#define STG_B  (3 * BUF_B)      // Ahi, Alo, W
#define GEMM_SMEM (2 * STG_B)   // 61440

__device__ __forceinline__ void g2s_chunk(uint32_t sbase,
    const __half* __restrict__ A0, const __half* __restrict__ A1,
    const __half* __restrict__ W, int K, int k0, int tid)
{
#pragma unroll
    for (int b = 0; b < 3; b++) {
        const __half* src = (b == 0) ? A0 : (b == 1) ? A1 : W;
#pragma unroll
        for (int j = 0; j < 2; j++) {
            int idx = tid + j * 256;
            int r = idx >> 2, q = idx & 3;
            cpa16(sbase + b * BUF_B + r * 80 + q * 16,
                  src + (size_t)r * K + k0 + q * 8);
        }
    }
}

__global__ void __launch_bounds__(256, 2)
gemm_mma2(const __half* __restrict__ Ahi, const __half* __restrict__ Alo,
          const __half* __restrict__ W, float* __restrict__ C,
          int M, int N, int K)
{
    extern __shared__ char smraw[];
    const uint32_t sb = smem_u32(smraw);

    const int tid  = threadIdx.x;
    const int wid  = tid >> 5;
    const int lane = tid & 31;
    const int wm   = wid >> 2;
    const int wn   = wid & 3;
    const int m0   = blockIdx.y << 7;
    const int n0   = blockIdx.x << 7;

    const __half* pA0 = Ahi + (size_t)m0 * K;
    const __half* pA1 = Alo + (size_t)m0 * K;
    const __half* pW  = W   + (size_t)n0 * K;

    float c[4][4][4];
#pragma unroll
    for (int a = 0; a < 4; a++)
#pragma unroll
        for (int b = 0; b < 4; b++)
#pragma unroll
            for (int d = 0; d < 4; d++) c[a][b][d] = 0.f;

    const int a_roff = (lane & 7) + ((lane >> 3) & 1) * 8;
    const int a_koff = ((lane >> 4) & 1) * 8;
    const int b_roff = (lane & 7) + ((lane >> 4) & 1) * 8;
    const int b_koff = ((lane >> 3) & 1) * 8;

    const int nch = K >> 5;

    g2s_chunk(sb, pA0, pA1, pW, K, 0, tid);
    asm volatile("cp.async.commit_group;" ::: "memory");

    for (int i = 0; i < nch; i++) {
        if (i + 1 < nch) {
            g2s_chunk(sb + ((i + 1) & 1) * STG_B, pA0, pA1, pW, K, (i + 1) << 5, tid);
            asm volatile("cp.async.commit_group;" ::: "memory");
            asm volatile("cp.async.wait_group 1;" ::: "memory");
        } else {
            asm volatile("cp.async.wait_group 0;" ::: "memory");
        }
        __syncthreads();

        const uint32_t st  = sb + (i & 1) * STG_B;
        const uint32_t sAh = st +            (wm * 64 + a_roff) * 80 + a_koff * 2;
        const uint32_t sAl = sAh + BUF_B;
        const uint32_t sW  = st + 2 * BUF_B + (wn * 32 + b_roff) * 80 + b_koff * 2;

#pragma unroll
        for (int ks = 0; ks < 2; ks++) {
            const int kb = ks * 32;
            uint32_t ah[4][4], al[4][4], bw[2][4];
#pragma unroll
            for (int mi = 0; mi < 4; mi++) ldm4(ah[mi], sAh + mi * 16 * 80 + kb);
#pragma unroll
            for (int np = 0; np < 2; np++) ldm4(bw[np], sW + np * 16 * 80 + kb);
#pragma unroll
            for (int mi = 0; mi < 4; mi++) ldm4(al[mi], sAl + mi * 16 * 80 + kb);

#pragma unroll
            for (int mi = 0; mi < 4; mi++)
#pragma unroll
                for (int np = 0; np < 2; np++) {
                    mma16816(c[mi][np * 2],     ah[mi], bw[np][0], bw[np][1]);
                    mma16816(c[mi][np * 2 + 1], ah[mi], bw[np][2], bw[np][3]);
                    mma16816(c[mi][np * 2],     al[mi], bw[np][0], bw[np][1]);
                    mma16816(c[mi][np * 2 + 1], al[mi], bw[np][2], bw[np][3]);
                }
        }
        __syncthreads();
    }

    const int g  = lane >> 2;
    const int i2 = (lane & 3) * 2;
#pragma unroll
    for (int mi = 0; mi < 4; mi++)
#pragma unroll
        for (int ni = 0; ni < 4; ni++) {
            float* p = C + (size_t)(m0 + wm * 64 + mi * 16 + g) * N
                         + n0 + wn * 32 + ni * 8 + i2;
            *(float2*)p           = make_float2(c[mi][ni][0], c[mi][ni][1]);
            *(float2*)(p + 8 * N) = make_float2(c[mi][ni][2], c[mi][ni][3]);
        }
}

// ===================================================================
// RoPE + split Q (fp16 hi/lo), RoPE K (fp16), convert V (fp16)
// Source: fused QKV buffer [MROWS, 3072]
// ===================================================================
__global__ void rope_split_q(const float* __restrict__ QKV,
                             const float* __restrict__ cs, const float* __restrict__ sn,
                             __half* __restrict__ Qh, __half* __restrict__ Ql, int total)
{
    int idx = blockIdx.x * blockDim.x + threadIdx.x;
    if (idx >= total) return;
    int d   = idx & 31;
    int hh  = (idx >> 5) & (NH - 1);
    int row = idx >> 10;

    float c1 = cs[row * 64 + d],      s1 = sn[row * 64 + d];
    float c2 = cs[row * 64 + d + 32], s2 = sn[row * 64 + d + 32];
    const float* p = QKV + (size_t)row * NQKV + hh * 64;
    float x1 = p[d], x2 = p[d + 32];
    float y1 = (x1 * c1 - x2 * s1) * QK_SCALE;
    float y2 = (x2 * c2 + x1 * s2) * QK_SCALE;

    int bb = row >> 11, ss = row & (SEQ - 1);
    size_t o = ((size_t)(bb * NH + hh) * SEQ + ss) * 64;
    __half h1 = __float2half_rn(y1);
    Qh[o + d]      = h1;
    Ql[o + d]      = __float2half_rn(y1 - __half2float(h1));
    __half h2 = __float2half_rn(y2);
    Qh[o + d + 32] = h2;
    Ql[o + d + 32] = __float2half_rn(y2 - __half2float(h2));
}

__global__ void rope_k(const float* __restrict__ QKV,
                       const float* __restrict__ cs, const float* __restrict__ sn,
                       __half* __restrict__ Kh, int total)
{
    int idx = blockIdx.x * blockDim.x + threadIdx.x;
    if (idx >= total) return;
    int d   = idx & 31;
    int kvh = (idx >> 5) & (NKVH - 1);
    int row = idx >> 8;

    float c1 = cs[row * 64 + d],      s1 = sn[row * 64 + d];
    float c2 = cs[row * 64 + d + 32], s2 = sn[row * 64 + d + 32];
    const float* p = QKV + (size_t)row * NQKV + 2048 + kvh * 64;
    float x1 = p[d], x2 = p[d + 32];

    int bb = row >> 11, ss = row & (SEQ - 1);
    size_t o = ((size_t)(bb * NKVH + kvh) * SEQ + ss) * 64;
    Kh[o + d]      = __float2half_rn(x1 * c1 - x2 * s1);
    Kh[o + d + 32] = __float2half_rn(x2 * c2 + x1 * s2);
}

__global__ void conv_v(const float* __restrict__ QKV, __half* __restrict__ Vh, int total4)
{
    int idx = blockIdx.x * blockDim.x + threadIdx.x;
    if (idx >= total4) return;
    int d4  = idx & 15;
    int kvh = (idx >> 4) & (NKVH - 1);
    int row = idx >> 7;
    float4 v = *(const float4*)(QKV + (size_t)row * NQKV + 2560 + kvh * 64 + d4 * 4);
    int bb = row >> 11, ss = row & (SEQ - 1);
    size_t o = ((size_t)(bb * NKVH + kvh) * SEQ + ss) * 64 + d4 * 4;
    *(__half2*)(Vh + o)     = __halves2half2(__float2half_rn(v.x), __float2half_rn(v.y));
    *(__half2*)(Vh + o + 2) = __halves2half2(__float2half_rn(v.z), __float2half_rn(v.w));
}

// ===================================================================
// Flash attention v3: 128 q-rows x 64 kv, 8 warps, 2-pass fp16.
// Writes fp16 hi/lo O directly (feeds out-projection).
// ===================================================================
#define FROWB 144
#define FT64  (64 * FROWB)     // 9216
#define FT128 (128 * FROWB)    // 18432
#define FL_SMEM (2 * FT128 + 4 * FT64)   // 73728

__global__ void __launch_bounds__(256, 2)
flash3(const __half* __restrict__ Qh, const __half* __restrict__ Ql,
       const __half* __restrict__ Kh, const __half* __restrict__ Vh,
       __half* __restrict__ Oh, __half* __restrict__ Ol)
{
    extern __shared__ char smraw[];
    const uint32_t sb = smem_u32(smraw);
    const int qt  = (int)gridDim.x - 1 - (int)blockIdx.x;  // heavy tiles first
    const int h   = blockIdx.y, b = blockIdx.z;
    const int kvh = h >> 2;
    const int tid = threadIdx.x, wid = tid >> 5, lane = tid & 31;

    const size_t qoff = ((size_t)(b * NH + h) * SEQ + (size_t)qt * 128) * 64;
    const size_t kvo  = (size_t)(b * NKVH + kvh) * SEQ * 64;
    const __half* kh = Kh + kvo;
    const __half* vh = Vh + kvo;

    // Q tiles (hi, lo): 128 rows x 64
#pragma unroll
    for (int t = 0; t < 8; t++) {
        int id  = tid + t * 256;
        int mat = id >> 10, rem = id & 1023, r = rem >> 3, q = rem & 7;
        cpa16(sb + mat * FT128 + r * FROWB + q * 16,
              (mat ? Ql : Qh) + qoff + r * 64 + q * 8);
    }
    // KV stage 0
#pragma unroll
    for (int t = 0; t < 4; t++) {
        int id  = tid + t * 256;
        int mat = id >> 9, rem = id & 511, r = rem >> 3, q = rem & 7;
        cpa16(sb + 2 * FT128 + mat * FT64 + r * FROWB + q * 16,
              (mat ? vh : kh) + (size_t)r * 64 + q * 8);
    }
    asm volatile("cp.async.commit_group;" ::: "memory");

    const int a_roff = (lane & 7) + ((lane >> 3) & 1) * 8;
    const int a_koff = ((lane >> 4) & 1) * 8;
    const int b_roff = (lane & 7) + ((lane >> 4) & 1) * 8;
    const int b_koff = ((lane >> 3) & 1) * 8;
    const int v_k    = (lane & 7) + ((lane >> 3) & 1) * 8;
    const int v_d    = ((lane >> 4) & 1) * 8;
    const uint32_t qa_h = sb + (wid * 16 + a_roff) * FROWB + a_koff * 2;
    const uint32_t qa_l = qa_h + FT128;

    float o[8][4];
#pragma unroll
    for (int t = 0; t < 8; t++)
#pragma unroll
        for (int e = 0; e < 4; e++) o[t][e] = 0.f;
    float m0 = -1e30f, m1 = -1e30f, l0 = 0.f, l1 = 0.f;

    const int jmax = 2 * qt + 1;
    const int rg0  = qt * 128 + wid * 16 + (lane >> 2);   // global q row

    for (int j = 0; j <= jmax; j++) {
        if (j < jmax) {
#pragma unroll
            for (int t = 0; t < 4; t++) {
                int id  = tid + t * 256;
                int mat = id >> 9, rem = id & 511, r = rem >> 3, q = rem & 7;
                cpa16(sb + 2 * FT128 + ((j + 1) & 1) * 2 * FT64 + mat * FT64
                          + r * FROWB + q * 16,
                      (mat ? vh : kh) + (size_t)((j + 1) * 64 + r) * 64 + q * 8);
            }
            asm volatile("cp.async.commit_group;" ::: "memory");
            asm volatile("cp.async.wait_group 1;" ::: "memory");
        } else {
            asm volatile("cp.async.wait_group 0;" ::: "memory");
        }
        __syncthreads();
        const uint32_t st_k = sb + 2 * FT128 + (j & 1) * 2 * FT64;
        const uint32_t st_v = st_k + FT64;

        // ---- S = Q K^T (2-pass: Qhi + Qlo vs fp16 K) ----
        float s[8][4];
#pragma unroll
        for (int t = 0; t < 8; t++)
#pragma unroll
            for (int e = 0; e < 4; e++) s[t][e] = 0.f;

#pragma unroll
        for (int ks = 0; ks < 4; ks++) {
            const uint32_t kb = ks * 32;
            uint32_t ah[4], al[4];
            ldm4(ah, qa_h + kb);
            ldm4(al, qa_l + kb);
#pragma unroll
            for (int ng = 0; ng < 4; ng++) {
                uint32_t kf[4];
                ldm4(kf, st_k + (ng * 16 + b_roff) * FROWB + b_koff * 2 + kb);
                mma16816(s[2 * ng],     ah, kf[0], kf[1]);
                mma16816(s[2 * ng + 1], ah, kf[2], kf[3]);
                mma16816(s[2 * ng],     al, kf[0], kf[1]);
                mma16816(s[2 * ng + 1], al, kf[2], kf[3]);
            }
        }

        // ---- causal mask (only near-diagonal tiles need it) ----
        if (j >= 2 * qt) {
#pragma unroll
            for (int t = 0; t < 8; t++) {
                int cg = j * 64 + t * 8 + (lane & 3) * 2;
                if (cg     > rg0)     s[t][0] = -1e30f;
                if (cg + 1 > rg0)     s[t][1] = -1e30f;
                if (cg     > rg0 + 8) s[t][2] = -1e30f;
                if (cg + 1 > rg0 + 8) s[t][3] = -1e30f;
            }
        }

        // ---- online softmax ----
        float mx0 = -1e30f, mx1 = -1e30f;
#pragma unroll
        for (int t = 0; t < 8; t++) {
            mx0 = fmaxf(mx0, fmaxf(s[t][0], s[t][1]));
            mx1 = fmaxf(mx1, fmaxf(s[t][2], s[t][3]));
        }
        mx0 = fmaxf(mx0, __shfl_xor_sync(0xffffffffu, mx0, 1));
        mx0 = fmaxf(mx0, __shfl_xor_sync(0xffffffffu, mx0, 2));
        mx1 = fmaxf(mx1, __shfl_xor_sync(0xffffffffu, mx1, 1));
        mx1 = fmaxf(mx1, __shfl_xor_sync(0xffffffffu, mx1, 2));
        float mn0 = fmaxf(m0, mx0), mn1 = fmaxf(m1, mx1);
        float al0 = fexp(m0 - mn0), al1 = fexp(m1 - mn1);
        m0 = mn0; m1 = mn1;
        float sum0 = 0.f, sum1 = 0.f;
#pragma unroll
        for (int t = 0; t < 8; t++) {
            s[t][0] = fexp(s[t][0] - mn0); sum0 += s[t][0];
            s[t][1] = fexp(s[t][1] - mn0); sum0 += s[t][1];
            s[t][2] = fexp(s[t][2] - mn1); sum1 += s[t][2];
            s[t][3] = fexp(s[t][3] - mn1); sum1 += s[t][3];
        }
        l0 = l0 * al0 + sum0;
        l1 = l1 * al1 + sum1;
#pragma unroll
        for (int t = 0; t < 8; t++) {
            o[t][0] *= al0; o[t][1] *= al0;
            o[t][2] *= al1; o[t][3] *= al1;
        }

        // ---- O += P V (2-pass: Phi + Plo vs fp16 V) ----
#pragma unroll
        for (int ks = 0; ks < 4; ks++) {
            uint32_t ph[4], pl[4];
#pragma unroll
            for (int half = 0; half < 2; half++) {
                const int t = 2 * ks + half;
#pragma unroll
                for (int rr = 0; rr < 2; rr++) {
                    float x0 = s[t][rr * 2], x1 = s[t][rr * 2 + 1];
                    __half h0 = __float2half_rn(x0);
                    __half h1 = __float2half_rn(x1);
                    __half2 H = __halves2half2(h0, h1);
                    __half2 L = __halves2half2(__float2half_rn(x0 - __half2float(h0)),
                                               __float2half_rn(x1 - __half2float(h1)));
                    ph[half * 2 + rr] = *(uint32_t*)&H;
                    pl[half * 2 + rr] = *(uint32_t*)&L;
                }
            }
#pragma unroll
            for (int dg = 0; dg < 4; dg++) {
                uint32_t vf[4];
                ldm4t(vf, st_v + (ks * 16 + v_k) * FROWB + (dg * 16 + v_d) * 2);
                mma16816(o[2 * dg],     ph, vf[0], vf[1]);
                mma16816(o[2 * dg + 1], ph, vf[2], vf[3]);
                mma16816(o[2 * dg],     pl, vf[0], vf[1]);
                mma16816(o[2 * dg + 1], pl, vf[2], vf[3]);
            }
        }
        __syncthreads();
    }

    // ---- epilogue: normalize, split fp16 hi/lo, store ----
    l0 += __shfl_xor_sync(0xffffffffu, l0, 1);
    l0 += __shfl_xor_sync(0xffffffffu, l0, 2);
    l1 += __shfl_xor_sync(0xffffffffu, l1, 1);
    l1 += __shfl_xor_sync(0xffffffffu, l1, 2);
    float inv0 = 1.f / l0, inv1 = 1.f / l1;

    const size_t base = ((size_t)b * SEQ + rg0 - /*local*/ 0) * DMODEL;  // rg0 is global row
    __half* oh0 = Oh + ((size_t)b * SEQ + rg0) * DMODEL + h * 64 + (lane & 3) * 2;
    __half* ol0 = Ol + ((size_t)b * SEQ + rg0) * DMODEL + h * 64 + (lane & 3) * 2;
    (void)base;
#pragma unroll
    for (int t = 0; t < 8; t++) {
        float x0 = o[t][0] * inv0, x1 = o[t][1] * inv0;
        __half h0 = __float2half_rn(x0), h1 = __float2half_rn(x1);
        *(__half2*)(oh0 + t * 8) = __halves2half2(h0, h1);
        *(__half2*)(ol0 + t * 8) = __halves2half2(__float2half_rn(x0 - __half2float(h0)),
                                                  __float2half_rn(x1 - __half2float(h1)));
        float y0 = o[t][2] * inv1, y1 = o[t][3] * inv1;
        __half g0 = __float2half_rn(y0), g1 = __float2half_rn(y1);
        *(__half2*)(oh0 + 8 * DMODEL + t * 8) = __halves2half2(g0, g1);
        *(__half2*)(ol0 + 8 * DMODEL + t * 8) = __halves2half2(__float2half_rn(y0 - __half2float(g0)),
                                                               __float2half_rn(y1 - __half2float(g1)));
    }
}

// ===================================================================
// Launch: 0 hidden, 1 cos, 2 sin, 3 mask (unused), 4 Wq, 5 Wk, 6 Wv, 7 Wo
// ===================================================================
extern "C" void kernel_launch(void* const* d_in, const int* in_sizes, int n_in,
                              void* d_out, int out_size)
{
    const float* hs = (const float*)d_in[0];
    const float* cs = (const float*)d_in[1];
    const float* sn = (const float*)d_in[2];
    const float* Wq = (const float*)d_in[4];
    const float* Wk = (const float*)d_in[5];
    const float* Wv = (const float*)d_in[6];
    const float* Wo = (const float*)d_in[7];
    float* out = (float*)d_out;

    float* QKV;
    __half *ah, *al, *oh, *ol, *wh, *kh, *vh;
    cudaGetSymbolAddress((void**)&QKV, g_QKV);
    cudaGetSymbolAddress((void**)&ah, g_ah);
    cudaGetSymbolAddress((void**)&al, g_al);
    cudaGetSymbolAddress((void**)&oh, g_oh);
    cudaGetSymbolAddress((void**)&ol, g_ol);
    cudaGetSymbolAddress((void**)&wh, g_wh);
    cudaGetSymbolAddress((void**)&kh, g_kh);
    cudaGetSymbolAddress((void**)&vh, g_vh);

    cudaFuncSetAttribute(gemm_mma2, cudaFuncAttributeMaxDynamicSharedMemorySize, GEMM_SMEM);
    cudaFuncSetAttribute(flash3,    cudaFuncAttributeMaxDynamicSharedMemorySize, FL_SMEM);

    const int actN4 = MROWS * DMODEL / 4;                // 2097152
    const int wBig4 = DMODEL * DMODEL / 4;               // 1048576
    const int wKV4  = (NKVH * HDIM) * DMODEL / 4;        // 262144

    // activations -> fp16 hi/lo
    split_fp16x2<<<(actN4 + 255) / 256, 256>>>(hs, ah, al, actN4);

    // weights -> fp16 fused [Wq; Wk; Wv]
    conv_fp16<<<(wBig4 + 255) / 256, 256>>>(Wq, wh, wBig4);
    conv_fp16<<<(wKV4 + 255) / 256, 256>>>(Wk, wh + (size_t)2048 * DMODEL, wKV4);
    conv_fp16<<<(wKV4 + 255) / 256, 256>>>(Wv, wh + (size_t)2560 * DMODEL, wKV4);

    // fused QKV projection
    gemm_mma2<<<dim3(NQKV / 128, MROWS / 128), 256, GEMM_SMEM>>>(
        ah, al, wh, QKV, MROWS, NQKV, DMODEL);

    // RoPE + splits (ah/al reused as Q hi/lo)
    {
        int totalQ = MROWS * NH * 32;
        rope_split_q<<<(totalQ + 255) / 256, 256>>>(QKV, cs, sn, ah, al, totalQ);
        int totalK = MROWS * NKVH * 32;
        rope_k<<<(totalK + 255) / 256, 256>>>(QKV, cs, sn, kh, totalK);
        int totalV4 = MROWS * NKVH * 16;
        conv_v<<<(totalV4 + 255) / 256, 256>>>(QKV, vh, totalV4);
    }

    // attention (writes fp16 hi/lo O)
    flash3<<<dim3(SEQ / 128, NH, BSZ), 256, FL_SMEM>>>(ah, al, kh, vh, oh, ol);

    // output projection
    conv_fp16<<<(wBig4 + 255) / 256, 256>>>(Wo, wh, wBig4);
    gemm_mma2<<<dim3(DMODEL / 128, MROWS / 128), 256, GEMM_SMEM>>>(
        oh, ol, wh, out, MROWS, DMODEL, DMODEL);
}

// round 9
// speedup vs baseline: 5.7385x; 1.2095x over previous
#include <cuda_runtime.h>
#include <cuda_fp16.h>
#include <cstdint>

// Problem constants
#define BSZ   2
#define SEQ   2048
#define DMODEL 2048
#define NH    32
#define NKVH  8
#define HDIM  64
#define QK_SCALE 0.125f
#define MROWS (BSZ*SEQ)   // 4096
#define NQKV  3072

// -------- scratch (static device globals: allocation-free) --------
__device__ __half g_ah[(size_t)MROWS * DMODEL];           // act hi
__device__ __half g_al[(size_t)MROWS * DMODEL];           // act lo
__device__ __half g_oh[(size_t)MROWS * DMODEL];           // O fp16
__device__ __half g_wh[(size_t)NQKV * DMODEL];            // weights fp16
__device__ __half g_qh[(size_t)BSZ * NH * SEQ * HDIM];    // Q hi [B,H,S,64]
__device__ __half g_ql[(size_t)BSZ * NH * SEQ * HDIM];    // Q lo
__device__ __half g_kh[(size_t)BSZ * NKVH * SEQ * HDIM];  // K fp16
__device__ __half g_vh[(size_t)BSZ * NKVH * SEQ * HDIM];  // V fp16

// ===================================================================
// Helpers
// ===================================================================
__device__ __forceinline__ uint32_t smem_u32(const void* p) {
    uint32_t a;
    asm("{ .reg .u64 t; cvta.to.shared.u64 t, %1; cvt.u32.u64 %0, t; }" : "=r"(a) : "l"(p));
    return a;
}
__device__ __forceinline__ void ldm4(uint32_t* r, uint32_t addr) {
    asm volatile("ldmatrix.sync.aligned.m8n8.x4.shared.b16 {%0,%1,%2,%3}, [%4];"
                 : "=r"(r[0]), "=r"(r[1]), "=r"(r[2]), "=r"(r[3]) : "r"(addr));
}
__device__ __forceinline__ void ldm4t(uint32_t* r, uint32_t addr) {
    asm volatile("ldmatrix.sync.aligned.m8n8.x4.trans.shared.b16 {%0,%1,%2,%3}, [%4];"
                 : "=r"(r[0]), "=r"(r[1]), "=r"(r[2]), "=r"(r[3]) : "r"(addr));
}
__device__ __forceinline__ void mma16816(float* c, const uint32_t* a,
                                         uint32_t b0, uint32_t b1) {
    asm volatile(
        "mma.sync.aligned.m16n8k16.row.col.f32.f16.f16.f32 "
        "{%0,%1,%2,%3}, {%4,%5,%6,%7}, {%8,%9}, {%0,%1,%2,%3};"
        : "+f"(c[0]), "+f"(c[1]), "+f"(c[2]), "+f"(c[3])
        : "r"(a[0]), "r"(a[1]), "r"(a[2]), "r"(a[3]), "r"(b0), "r"(b1));
}
__device__ __forceinline__ void cpa16(uint32_t d, const void* s) {
    asm volatile("cp.async.cg.shared.global [%0], [%1], 16;" :: "r"(d), "l"(s) : "memory");
}
__device__ __forceinline__ float fexp(float x) {
    float y = fmaxf(x, -87.0f) * 1.4426950408889634f;
    int   n = __float2int_rn(y);
    float f = y - (float)n;
    float p = 1.3333558146e-3f;
    p = fmaf(p, f, 9.6181291081e-3f);
    p = fmaf(p, f, 5.5504108664e-2f);
    p = fmaf(p, f, 2.4022650696e-1f);
    p = fmaf(p, f, 6.9314718056e-1f);
    p = fmaf(p, f, 1.0f);
    return __int_as_float((n + 127) << 23) * p;
}

// ===================================================================
// elementwise converters
// ===================================================================
__global__ void split_fp16x2(const float* __restrict__ x,
                             __half* __restrict__ hi, __half* __restrict__ lo, int n4)
{
    int i = blockIdx.x * blockDim.x + threadIdx.x;
    if (i >= n4) return;
    float4 v = ((const float4*)x)[i];
    __half h0 = __float2half_rn(v.x), h1 = __float2half_rn(v.y);
    __half h2 = __float2half_rn(v.z), h3 = __float2half_rn(v.w);
    __half2* H = (__half2*)hi;
    __half2* L = (__half2*)lo;
    H[2 * i]     = __halves2half2(h0, h1);
    H[2 * i + 1] = __halves2half2(h2, h3);
    L[2 * i]     = __halves2half2(__float2half_rn(v.x - __half2float(h0)),
                                  __float2half_rn(v.y - __half2float(h1)));
    L[2 * i + 1] = __halves2half2(__float2half_rn(v.z - __half2float(h2)),
                                  __float2half_rn(v.w - __half2float(h3)));
}
__global__ void conv_fp16(const float* __restrict__ x, __half* __restrict__ y, int n4)
{
    int i = blockIdx.x * blockDim.x + threadIdx.x;
    if (i >= n4) return;
    float4 v = ((const float4*)x)[i];
    __half2* Y = (__half2*)y;
    Y[2 * i]     = __halves2half2(__float2half_rn(v.x), __float2half_rn(v.y));
    Y[2 * i + 1] = __halves2half2(__float2half_rn(v.z), __float2half_rn(v.w));
}

// ===================================================================
// QKV GEMM: 2-pass fp16, CTA 128x128, 4 warps (2m x 2n), warp 64x64.
// Fused epilogue: RoPE + scale + hi/lo split + [B,H,S,64] transpose.
// ===================================================================
#define GBUF 10240               // 128 rows * 80 B
#define QKV_STG (3 * GBUF)
#define QKV_SMEM (2 * QKV_STG)   // 61440

__device__ __forceinline__ void qkv_g2s(uint32_t sbase,
    const __half* __restrict__ A0, const __half* __restrict__ A1,
    const __half* __restrict__ W, int k0, int tid)
{
#pragma unroll
    for (int b = 0; b < 3; b++) {
        const __half* src = (b == 0) ? A0 : (b == 1) ? A1 : W;
#pragma unroll
        for (int j = 0; j < 4; j++) {
            int idx = tid + j * 128;
            int r = idx >> 2, q = idx & 3;
            cpa16(sbase + b * GBUF + r * 80 + q * 16,
                  src + (size_t)r * DMODEL + k0 + q * 8);
        }
    }
}

__global__ void __launch_bounds__(128, 2)
gemm_qkv(const __half* __restrict__ Ahi, const __half* __restrict__ Alo,
         const __half* __restrict__ W,
         const float* __restrict__ cs, const float* __restrict__ sn,
         __half* __restrict__ Qh, __half* __restrict__ Ql,
         __half* __restrict__ Kh, __half* __restrict__ Vh)
{
    extern __shared__ char smraw[];
    const uint32_t sb = smem_u32(smraw);
    const int tid  = threadIdx.x;
    const int wid  = tid >> 5;
    const int lane = tid & 31;
    const int wm   = wid >> 1;
    const int wn   = wid & 1;
    const int m0   = blockIdx.y << 7;
    const int n0   = blockIdx.x << 7;

    const __half* pA0 = Ahi + (size_t)m0 * DMODEL;
    const __half* pA1 = Alo + (size_t)m0 * DMODEL;
    const __half* pW  = W   + (size_t)n0 * DMODEL;

    float c[4][8][4];
#pragma unroll
    for (int a = 0; a < 4; a++)
#pragma unroll
        for (int b = 0; b < 8; b++)
#pragma unroll
            for (int d = 0; d < 4; d++) c[a][b][d] = 0.f;

    const int a_roff = (lane & 7) + ((lane >> 3) & 1) * 8;
    const int a_koff = ((lane >> 4) & 1) * 8;
    const int b_roff = (lane & 7) + ((lane >> 4) & 1) * 8;
    const int b_koff = ((lane >> 3) & 1) * 8;

    const int nch = DMODEL >> 5;   // 64

    qkv_g2s(sb, pA0, pA1, pW, 0, tid);
    asm volatile("cp.async.commit_group;" ::: "memory");

    for (int i = 0; i < nch; i++) {
        if (i + 1 < nch) {
            qkv_g2s(sb + ((i + 1) & 1) * QKV_STG, pA0, pA1, pW, (i + 1) << 5, tid);
            asm volatile("cp.async.commit_group;" ::: "memory");
            asm volatile("cp.async.wait_group 1;" ::: "memory");
        } else {
            asm volatile("cp.async.wait_group 0;" ::: "memory");
        }
        __syncthreads();

        const uint32_t st  = sb + (i & 1) * QKV_STG;
        const uint32_t sAh = st +            (wm * 64 + a_roff) * 80 + a_koff * 2;
        const uint32_t sAl = sAh + GBUF;
        const uint32_t sW  = st + 2 * GBUF + (wn * 64 + b_roff) * 80 + b_koff * 2;

#pragma unroll
        for (int ks = 0; ks < 2; ks++) {
            const int kb = ks * 32;
            uint32_t ah[4][4], al[4][4], bw[4][4];
#pragma unroll
            for (int mi = 0; mi < 4; mi++) ldm4(ah[mi], sAh + mi * 1280 + kb);
#pragma unroll
            for (int n4 = 0; n4 < 4; n4++) ldm4(bw[n4], sW + n4 * 1280 + kb);
#pragma unroll
            for (int mi = 0; mi < 4; mi++) ldm4(al[mi], sAl + mi * 1280 + kb);

#pragma unroll
            for (int mi = 0; mi < 4; mi++)
#pragma unroll
                for (int n4 = 0; n4 < 4; n4++) {
                    mma16816(c[mi][n4 * 2],     ah[mi], bw[n4][0], bw[n4][1]);
                    mma16816(c[mi][n4 * 2 + 1], ah[mi], bw[n4][2], bw[n4][3]);
                    mma16816(c[mi][n4 * 2],     al[mi], bw[n4][0], bw[n4][1]);
                    mma16816(c[mi][n4 * 2 + 1], al[mi], bw[n4][2], bw[n4][3]);
                }
        }
        __syncthreads();
    }

    // -------- fused epilogue --------
    const int gn    = n0 + wn * 64;          // warp covers exactly one head
    const int rbase = m0 + wm * 64 + (lane >> 2);
    const int cb    = (lane & 3) * 2;

    if (gn < 2048) {
        // Q head: RoPE + scale + hi/lo split
        const int h = gn >> 6;
#pragma unroll
        for (int mi = 0; mi < 4; mi++)
#pragma unroll
            for (int hf = 0; hf < 2; hf++) {
                const int e = hf * 2;
                const int m = rbase + mi * 16 + hf * 8;
                const int bb = m >> 11, s = m & (SEQ - 1);
                const float* cp = cs + s * 64;
                const float* sp = sn + s * 64;
                const size_t ob = ((size_t)(bb * NH + h) * SEQ + s) * 64;
#pragma unroll
                for (int ni = 0; ni < 4; ni++) {
                    const int d = ni * 8 + cb;
                    float2 c1 = *(const float2*)(cp + d);
                    float2 s1 = *(const float2*)(sp + d);
                    float2 c2 = *(const float2*)(cp + d + 32);
                    float2 s2 = *(const float2*)(sp + d + 32);
                    float x1a = c[mi][ni][e],     x1b = c[mi][ni][e + 1];
                    float x2a = c[mi][ni + 4][e], x2b = c[mi][ni + 4][e + 1];
                    float y1a = (x1a * c1.x - x2a * s1.x) * QK_SCALE;
                    float y1b = (x1b * c1.y - x2b * s1.y) * QK_SCALE;
                    float y2a = (x2a * c2.x + x1a * s2.x) * QK_SCALE;
                    float y2b = (x2b * c2.y + x1b * s2.y) * QK_SCALE;
                    __half h1a = __float2half_rn(y1a), h1b = __float2half_rn(y1b);
                    *(__half2*)(Qh + ob + d) = __halves2half2(h1a, h1b);
                    *(__half2*)(Ql + ob + d) =
                        __halves2half2(__float2half_rn(y1a - __half2float(h1a)),
                                       __float2half_rn(y1b - __half2float(h1b)));
                    __half h2a = __float2half_rn(y2a), h2b = __float2half_rn(y2b);
                    *(__half2*)(Qh + ob + d + 32) = __halves2half2(h2a, h2b);
                    *(__half2*)(Ql + ob + d + 32) =
                        __halves2half2(__float2half_rn(y2a - __half2float(h2a)),
                                       __float2half_rn(y2b - __half2float(h2b)));
                }
            }
    } else if (gn < 2560) {
        // K head: RoPE, single fp16
        const int kvh = (gn - 2048) >> 6;
#pragma unroll
        for (int mi = 0; mi < 4; mi++)
#pragma unroll
            for (int hf = 0; hf < 2; hf++) {
                const int e = hf * 2;
                const int m = rbase + mi * 16 + hf * 8;
                const int bb = m >> 11, s = m & (SEQ - 1);
                const float* cp = cs + s * 64;
                const float* sp = sn + s * 64;
                const size_t ob = ((size_t)(bb * NKVH + kvh) * SEQ + s) * 64;
#pragma unroll
                for (int ni = 0; ni < 4; ni++) {
                    const int d = ni * 8 + cb;
                    float2 c1 = *(const float2*)(cp + d);
                    float2 s1 = *(const float2*)(sp + d);
                    float2 c2 = *(const float2*)(cp + d + 32);
                    float2 s2 = *(const float2*)(sp + d + 32);
                    float x1a = c[mi][ni][e],     x1b = c[mi][ni][e + 1];
                    float x2a = c[mi][ni + 4][e], x2b = c[mi][ni + 4][e + 1];
                    *(__half2*)(Kh + ob + d) =
                        __halves2half2(__float2half_rn(x1a * c1.x - x2a * s1.x),
                                       __float2half_rn(x1b * c1.y - x2b * s1.y));
                    *(__half2*)(Kh + ob + d + 32) =
                        __halves2half2(__float2half_rn(x2a * c2.x + x1a * s2.x),
                                       __float2half_rn(x2b * c2.y + x1b * s2.y));
                }
            }
    } else {
        // V head: plain fp16
        const int kvh = (gn - 2560) >> 6;
#pragma unroll
        for (int mi = 0; mi < 4; mi++)
#pragma unroll
            for (int hf = 0; hf < 2; hf++) {
                const int e = hf * 2;
                const int m = rbase + mi * 16 + hf * 8;
                const int bb = m >> 11, s = m & (SEQ - 1);
                const size_t ob = ((size_t)(bb * NKVH + kvh) * SEQ + s) * 64;
#pragma unroll
                for (int ni = 0; ni < 8; ni++) {
                    const int d = ni * 8 + cb;
                    *(__half2*)(Vh + ob + d) =
                        __halves2half2(__float2half_rn(c[mi][ni][e]),
                                       __float2half_rn(c[mi][ni][e + 1]));
                }
            }
    }
}

// ===================================================================
// Out-projection GEMM: 1-pass fp16 (A = O fp16), CTA 128x128, 4 warps 64x64.
// ===================================================================
#define OUT_STG (2 * GBUF)
#define OUT_SMEM (2 * OUT_STG)   // 40960

__global__ void __launch_bounds__(128, 2)
gemm_out(const __half* __restrict__ A, const __half* __restrict__ W,
         float* __restrict__ C)
{
    extern __shared__ char smraw[];
    const uint32_t sb = smem_u32(smraw);
    const int tid  = threadIdx.x;
    const int wid  = tid >> 5;
    const int lane = tid & 31;
    const int wm   = wid >> 1;
    const int wn   = wid & 1;
    const int m0   = blockIdx.y << 7;
    const int n0   = blockIdx.x << 7;

    const __half* pA = A + (size_t)m0 * DMODEL;
    const __half* pW = W + (size_t)n0 * DMODEL;

    float c[4][8][4];
#pragma unroll
    for (int a = 0; a < 4; a++)
#pragma unroll
        for (int b = 0; b < 8; b++)
#pragma unroll
            for (int d = 0; d < 4; d++) c[a][b][d] = 0.f;

    const int a_roff = (lane & 7) + ((lane >> 3) & 1) * 8;
    const int a_koff = ((lane >> 4) & 1) * 8;
    const int b_roff = (lane & 7) + ((lane >> 4) & 1) * 8;
    const int b_koff = ((lane >> 3) & 1) * 8;

    const int nch = DMODEL >> 5;

    // stage 0 load
#pragma unroll
    for (int b = 0; b < 2; b++) {
        const __half* src = b ? pW : pA;
#pragma unroll
        for (int j = 0; j < 4; j++) {
            int idx = tid + j * 128;
            int r = idx >> 2, q = idx & 3;
            cpa16(sb + b * GBUF + r * 80 + q * 16, src + (size_t)r * DMODEL + q * 8);
        }
    }
    asm volatile("cp.async.commit_group;" ::: "memory");

    for (int i = 0; i < nch; i++) {
        if (i + 1 < nch) {
            const int k0 = (i + 1) << 5;
            const uint32_t dst = sb + ((i + 1) & 1) * OUT_STG;
#pragma unroll
            for (int b = 0; b < 2; b++) {
                const __half* src = b ? pW : pA;
#pragma unroll
                for (int j = 0; j < 4; j++) {
                    int idx = tid + j * 128;
                    int r = idx >> 2, q = idx & 3;
                    cpa16(dst + b * GBUF + r * 80 + q * 16,
                          src + (size_t)r * DMODEL + k0 + q * 8);
                }
            }
            asm volatile("cp.async.commit_group;" ::: "memory");
            asm volatile("cp.async.wait_group 1;" ::: "memory");
        } else {
            asm volatile("cp.async.wait_group 0;" ::: "memory");
        }
        __syncthreads();

        const uint32_t st  = sb + (i & 1) * OUT_STG;
        const uint32_t sA  = st +        (wm * 64 + a_roff) * 80 + a_koff * 2;
        const uint32_t sW  = st + GBUF + (wn * 64 + b_roff) * 80 + b_koff * 2;

#pragma unroll
        for (int ks = 0; ks < 2; ks++) {
            const int kb = ks * 32;
            uint32_t ah[4][4], bw[4][4];
#pragma unroll
            for (int mi = 0; mi < 4; mi++) ldm4(ah[mi], sA + mi * 1280 + kb);
#pragma unroll
            for (int n4 = 0; n4 < 4; n4++) ldm4(bw[n4], sW + n4 * 1280 + kb);
#pragma unroll
            for (int mi = 0; mi < 4; mi++)
#pragma unroll
                for (int n4 = 0; n4 < 4; n4++) {
                    mma16816(c[mi][n4 * 2],     ah[mi], bw[n4][0], bw[n4][1]);
                    mma16816(c[mi][n4 * 2 + 1], ah[mi], bw[n4][2], bw[n4][3]);
                }
        }
        __syncthreads();
    }

    const int g  = lane >> 2;
    const int i2 = (lane & 3) * 2;
#pragma unroll
    for (int mi = 0; mi < 4; mi++)
#pragma unroll
        for (int ni = 0; ni < 8; ni++) {
            float* p = C + (size_t)(m0 + wm * 64 + mi * 16 + g) * DMODEL
                         + n0 + wn * 64 + ni * 8 + i2;
            *(float2*)p               = make_float2(c[mi][ni][0], c[mi][ni][1]);
            *(float2*)(p + 8 * DMODEL) = make_float2(c[mi][ni][2], c[mi][ni][3]);
        }
}

// ===================================================================
// Flash attention: 128 q x 64 kv, 8 warps; QK 2-pass, PV 1-pass.
// Writes O as plain fp16.
// ===================================================================
#define FROWB 144
#define FT64  (64 * FROWB)
#define FT128 (128 * FROWB)
#define FL_SMEM (2 * FT128 + 4 * FT64)   // 73728

__global__ void __launch_bounds__(256, 2)
flash3(const __half* __restrict__ Qh, const __half* __restrict__ Ql,
       const __half* __restrict__ Kh, const __half* __restrict__ Vh,
       __half* __restrict__ Oh)
{
    extern __shared__ char smraw[];
    const uint32_t sb = smem_u32(smraw);
    const int qt  = (int)gridDim.x - 1 - (int)blockIdx.x;
    const int h   = blockIdx.y, b = blockIdx.z;
    const int kvh = h >> 2;
    const int tid = threadIdx.x, wid = tid >> 5, lane = tid & 31;

    const size_t qoff = ((size_t)(b * NH + h) * SEQ + (size_t)qt * 128) * 64;
    const size_t kvo  = (size_t)(b * NKVH + kvh) * SEQ * 64;
    const __half* kh = Kh + kvo;
    const __half* vh = Vh + kvo;

#pragma unroll
    for (int t = 0; t < 8; t++) {
        int id  = tid + t * 256;
        int mat = id >> 10, rem = id & 1023, r = rem >> 3, q = rem & 7;
        cpa16(sb + mat * FT128 + r * FROWB + q * 16,
              (mat ? Ql : Qh) + qoff + r * 64 + q * 8);
    }
#pragma unroll
    for (int t = 0; t < 4; t++) {
        int id  = tid + t * 256;
        int mat = id >> 9, rem = id & 511, r = rem >> 3, q = rem & 7;
        cpa16(sb + 2 * FT128 + mat * FT64 + r * FROWB + q * 16,
              (mat ? vh : kh) + (size_t)r * 64 + q * 8);
    }
    asm volatile("cp.async.commit_group;" ::: "memory");

    const int a_roff = (lane & 7) + ((lane >> 3) & 1) * 8;
    const int a_koff = ((lane >> 4) & 1) * 8;
    const int b_roff = (lane & 7) + ((lane >> 4) & 1) * 8;
    const int b_koff = ((lane >> 3) & 1) * 8;
    const int v_k    = (lane & 7) + ((lane >> 3) & 1) * 8;
    const int v_d    = ((lane >> 4) & 1) * 8;
    const uint32_t qa_h = sb + (wid * 16 + a_roff) * FROWB + a_koff * 2;
    const uint32_t qa_l = qa_h + FT128;

    float o[8][4];
#pragma unroll
    for (int t = 0; t < 8; t++)
#pragma unroll
        for (int e = 0; e < 4; e++) o[t][e] = 0.f;
    float m0 = -1e30f, m1 = -1e30f, l0 = 0.f, l1 = 0.f;

    const int jmax = 2 * qt + 1;
    const int rg0  = qt * 128 + wid * 16 + (lane >> 2);

    for (int j = 0; j <= jmax; j++) {
        if (j < jmax) {
#pragma unroll
            for (int t = 0; t < 4; t++) {
                int id  = tid + t * 256;
                int mat = id >> 9, rem = id & 511, r = rem >> 3, q = rem & 7;
                cpa16(sb + 2 * FT128 + ((j + 1) & 1) * 2 * FT64 + mat * FT64
                          + r * FROWB + q * 16,
                      (mat ? vh : kh) + (size_t)((j + 1) * 64 + r) * 64 + q * 8);
            }
            asm volatile("cp.async.commit_group;" ::: "memory");
            asm volatile("cp.async.wait_group 1;" ::: "memory");
        } else {
            asm volatile("cp.async.wait_group 0;" ::: "memory");
        }
        __syncthreads();
        const uint32_t st_k = sb + 2 * FT128 + (j & 1) * 2 * FT64;
        const uint32_t st_v = st_k + FT64;

        // S = Q K^T (2-pass)
        float s[8][4];
#pragma unroll
        for (int t = 0; t < 8; t++)
#pragma unroll
            for (int e = 0; e < 4; e++) s[t][e] = 0.f;

#pragma unroll
        for (int ks = 0; ks < 4; ks++) {
            const uint32_t kb = ks * 32;
            uint32_t ah[4], al[4];
            ldm4(ah, qa_h + kb);
            ldm4(al, qa_l + kb);
#pragma unroll
            for (int ng = 0; ng < 4; ng++) {
                uint32_t kf[4];
                ldm4(kf, st_k + (ng * 16 + b_roff) * FROWB + b_koff * 2 + kb);
                mma16816(s[2 * ng],     ah, kf[0], kf[1]);
                mma16816(s[2 * ng + 1], ah, kf[2], kf[3]);
                mma16816(s[2 * ng],     al, kf[0], kf[1]);
                mma16816(s[2 * ng + 1], al, kf[2], kf[3]);
            }
        }

        if (j >= 2 * qt) {
#pragma unroll
            for (int t = 0; t < 8; t++) {
                int cg = j * 64 + t * 8 + (lane & 3) * 2;
                if (cg     > rg0)     s[t][0] = -1e30f;
                if (cg + 1 > rg0)     s[t][1] = -1e30f;
                if (cg     > rg0 + 8) s[t][2] = -1e30f;
                if (cg + 1 > rg0 + 8) s[t][3] = -1e30f;
            }
        }

        float mx0 = -1e30f, mx1 = -1e30f;
#pragma unroll
        for (int t = 0; t < 8; t++) {
            mx0 = fmaxf(mx0, fmaxf(s[t][0], s[t][1]));
            mx1 = fmaxf(mx1, fmaxf(s[t][2], s[t][3]));
        }
        mx0 = fmaxf(mx0, __shfl_xor_sync(0xffffffffu, mx0, 1));
        mx0 = fmaxf(mx0, __shfl_xor_sync(0xffffffffu, mx0, 2));
        mx1 = fmaxf(mx1, __shfl_xor_sync(0xffffffffu, mx1, 1));
        mx1 = fmaxf(mx1, __shfl_xor_sync(0xffffffffu, mx1, 2));
        float mn0 = fmaxf(m0, mx0), mn1 = fmaxf(m1, mx1);
        float al0 = fexp(m0 - mn0), al1 = fexp(m1 - mn1);
        m0 = mn0; m1 = mn1;
        float sum0 = 0.f, sum1 = 0.f;
#pragma unroll
        for (int t = 0; t < 8; t++) {
            s[t][0] = fexp(s[t][0] - mn0); sum0 += s[t][0];
            s[t][1] = fexp(s[t][1] - mn0); sum0 += s[t][1];
            s[t][2] = fexp(s[t][2] - mn1); sum1 += s[t][2];
            s[t][3] = fexp(s[t][3] - mn1); sum1 += s[t][3];
        }
        l0 = l0 * al0 + sum0;
        l1 = l1 * al1 + sum1;
#pragma unroll
        for (int t = 0; t < 8; t++) {
            o[t][0] *= al0; o[t][1] *= al0;
            o[t][2] *= al1; o[t][3] *= al1;
        }

        // O += P V (1-pass fp16 P)
#pragma unroll
        for (int ks = 0; ks < 4; ks++) {
            uint32_t ph[4];
#pragma unroll
            for (int half = 0; half < 2; half++) {
                const int t = 2 * ks + half;
#pragma unroll
                for (int rr = 0; rr < 2; rr++) {
                    __half2 H = __halves2half2(__float2half_rn(s[t][rr * 2]),
                                               __float2half_rn(s[t][rr * 2 + 1]));
                    ph[half * 2 + rr] = *(uint32_t*)&H;
                }
            }
#pragma unroll
            for (int dg = 0; dg < 4; dg++) {
                uint32_t vf[4];
                ldm4t(vf, st_v + (ks * 16 + v_k) * FROWB + (dg * 16 + v_d) * 2);
                mma16816(o[2 * dg],     ph, vf[0], vf[1]);
                mma16816(o[2 * dg + 1], ph, vf[2], vf[3]);
            }
        }
        __syncthreads();
    }

    l0 += __shfl_xor_sync(0xffffffffu, l0, 1);
    l0 += __shfl_xor_sync(0xffffffffu, l0, 2);
    l1 += __shfl_xor_sync(0xffffffffu, l1, 1);
    l1 += __shfl_xor_sync(0xffffffffu, l1, 2);
    float inv0 = 1.f / l0, inv1 = 1.f / l1;

    __half* oh0 = Oh + ((size_t)b * SEQ + rg0) * DMODEL + h * 64 + (lane & 3) * 2;
#pragma unroll
    for (int t = 0; t < 8; t++) {
        *(__half2*)(oh0 + t * 8) =
            __halves2half2(__float2half_rn(o[t][0] * inv0),
                           __float2half_rn(o[t][1] * inv0));
        *(__half2*)(oh0 + 8 * DMODEL + t * 8) =
            __halves2half2(__float2half_rn(o[t][2] * inv1),
                           __float2half_rn(o[t][3] * inv1));
    }
}

// ===================================================================
// Launch: 0 hidden, 1 cos, 2 sin, 3 mask (unused), 4 Wq, 5 Wk, 6 Wv, 7 Wo
// ===================================================================
extern "C" void kernel_launch(void* const* d_in, const int* in_sizes, int n_in,
                              void* d_out, int out_size)
{
    const float* hs = (const float*)d_in[0];
    const float* cs = (const float*)d_in[1];
    const float* sn = (const float*)d_in[2];
    const float* Wq = (const float*)d_in[4];
    const float* Wk = (const float*)d_in[5];
    const float* Wv = (const float*)d_in[6];
    const float* Wo = (const float*)d_in[7];
    float* out = (float*)d_out;

    __half *ah, *al, *oh, *wh, *qh, *ql, *kh, *vh;
    cudaGetSymbolAddress((void**)&ah, g_ah);
    cudaGetSymbolAddress((void**)&al, g_al);
    cudaGetSymbolAddress((void**)&oh, g_oh);
    cudaGetSymbolAddress((void**)&wh, g_wh);
    cudaGetSymbolAddress((void**)&qh, g_qh);
    cudaGetSymbolAddress((void**)&ql, g_ql);
    cudaGetSymbolAddress((void**)&kh, g_kh);
    cudaGetSymbolAddress((void**)&vh, g_vh);

    cudaFuncSetAttribute(gemm_qkv, cudaFuncAttributeMaxDynamicSharedMemorySize, QKV_SMEM);
    cudaFuncSetAttribute(gemm_out, cudaFuncAttributeMaxDynamicSharedMemorySize, OUT_SMEM);
    cudaFuncSetAttribute(flash3,   cudaFuncAttributeMaxDynamicSharedMemorySize, FL_SMEM);

    const int actN4 = MROWS * DMODEL / 4;
    const int wBig4 = DMODEL * DMODEL / 4;
    const int wKV4  = (NKVH * HDIM) * DMODEL / 4;

    // activations -> fp16 hi/lo
    split_fp16x2<<<(actN4 + 255) / 256, 256>>>(hs, ah, al, actN4);

    // fused weights [Wq; Wk; Wv] -> fp16
    conv_fp16<<<(wBig4 + 255) / 256, 256>>>(Wq, wh, wBig4);
    conv_fp16<<<(wKV4 + 255) / 256, 256>>>(Wk, wh + (size_t)2048 * DMODEL, wKV4);
    conv_fp16<<<(wKV4 + 255) / 256, 256>>>(Wv, wh + (size_t)2560 * DMODEL, wKV4);

    // fused QKV projection + RoPE + split + transpose
    gemm_qkv<<<dim3(NQKV / 128, MROWS / 128), 128, QKV_SMEM>>>(
        ah, al, wh, cs, sn, qh, ql, kh, vh);

    // attention
    flash3<<<dim3(SEQ / 128, NH, BSZ), 256, FL_SMEM>>>(qh, ql, kh, vh, oh);

    // output projection (1-pass)
    conv_fp16<<<(wBig4 + 255) / 256, 256>>>(Wo, wh, wBig4);
    gemm_out<<<dim3(DMODEL / 128, MROWS / 128), 128, OUT_SMEM>>>(oh, wh, out);
}